// round 3
// baseline (speedup 1.0000x reference)
#include <cuda_runtime.h>
#include <math.h>

#define HP   270
#define NPIX 72900
#define NB   2
#define ND   8
#define HIN  256

__device__ float  g_xp[NB*NPIX];
__device__ float2 g_X [NB*NPIX];
__device__ float2 g_T1[ND*NPIX];
__device__ float2 g_T2[ND*NPIX];
__device__ float2 g_Hf[NPIX];
__device__ float  g_S [NPIX];
__device__ float2 g_tw[HP];
__device__ float2 g_tempB[HP*15];
__device__ float2 g_tempG[24*HP*5];
__device__ float  g_ah[HP];
__device__ float  g_aw[HP];
__device__ float  g_z [ND*NPIX];
__device__ float  g_ww[24*25];
__device__ float  g_cw[32*25];
__device__ float  g_w1[5*64*32*9];
__device__ float  g_w2[5*32*64*9];
__device__ float  g_f0[ND*32*NPIX];
__device__ float  g_f1[ND*64*NPIX];
__device__ float  g_ct[ND*NPIX];
__device__ float  g_amp[4];
__device__ float  g_cstdn[ND];
__device__ float  g_nrm2[ND];
__device__ float  g_scl[ND];

static __device__ __forceinline__ int refl(int i, int n){
    if (i < 0)  i = -i - 1;
    if (i >= n) i = 2*n - 1 - i;
    return i;
}

__global__ void k_init_tw(){
    int t = threadIdx.x;
    if (t < HP){
        double ang = -2.0 * 3.14159265358979323846 * (double)t / (double)HP;
        double s, c; sincos(ang, &s, &c);
        g_tw[t] = make_float2((float)c, (float)s);
    }
}

__global__ void k_pad(const float* __restrict__ x){
    int p = blockIdx.x*256 + threadIdx.x;
    if (p >= NPIX) return;
    int b = blockIdx.y;
    int y = p / HP, xx = p - y*HP;
    g_xp[b*NPIX + p] = x[b*HIN*HIN + refl(y-7,HIN)*HIN + refl(xx-7,HIN)];
}

__global__ void k_alphas(const float* __restrict__ bk){
    __shared__ float ph[15], pw[15], rh[15], rw[15];
    int t = threadIdx.x;
    if (t < 15){
        float s = 0.f, q = 0.f;
        for (int j = 0; j < 15; ++j){ s += bk[t*15+j]; q += bk[j*15+t]; }
        ph[t] = s; pw[t] = q;
    }
    __syncthreads();
    if (t < 15){
        float s = 0.f, q = 0.f;
        for (int j = 0; j + t < 15; ++j){ s += ph[j]*ph[j+t]; q += pw[j]*pw[j+t]; }
        rh[t] = s; rw[t] = q;
    }
    __syncthreads();
    if (t < HP){
        float zh = 0.f, zw = 0.f;
        if (t <= 14)       { zh = rh[t];       zw = rw[t];       }
        else if (t >= 255) { zh = rh[269 - t]; zw = rw[269 - t]; }
        g_ah[t] = 1.f - zh / rh[0];
        g_aw[t] = 1.f - zw / rw[0];
    }
}

__global__ void k_psf1(const float* __restrict__ bk){
    int tid = blockIdx.x*256 + threadIdx.x;
    if (tid >= HP*15) return;
    int u = tid / 15, w = tid - u*15;
    float ax = 0.f, ay = 0.f;
    for (int h = 0; h < 15; ++h){
        int rr = (h >= 7) ? (h - 7) : (h + 263);
        float2 t = g_tw[(u*rr) % HP];
        float v = bk[h*15 + w];
        ax += v*t.x; ay += v*t.y;
    }
    g_tempB[tid] = make_float2(ax, ay);
}

__global__ void k_psf2(){
    int p = blockIdx.x*256 + threadIdx.x;
    if (p >= NPIX) return;
    int u = p / HP, v = p - u*HP;
    float ax = 0.f, ay = 0.f;
    for (int w = 0; w < 15; ++w){
        int rr = (w >= 7) ? (w - 7) : (w + 263);
        float2 t = g_tw[(v*rr) % HP];
        float2 b = g_tempB[u*15 + w];
        ax += b.x*t.x - b.y*t.y;
        ay += b.x*t.y + b.y*t.x;
    }
    g_Hf[p] = make_float2(ax, ay);
}

__global__ void k_wnorm(const float* __restrict__ w, const float* __restrict__ sc,
                        float* __restrict__ out, int sz){
    int ch = blockIdx.x;
    const float* src = w + (size_t)ch*sz;
    int lane = threadIdx.x;
    float s = 0.f;
    for (int i = lane; i < sz; i += 32) s += src[i];
    #pragma unroll
    for (int o = 16; o; o >>= 1) s += __shfl_xor_sync(0xffffffffu, s, o);
    float mean = s / (float)sz;
    float q = 0.f;
    for (int i = lane; i < sz; i += 32){ float v = src[i]-mean; q += v*v; }
    #pragma unroll
    for (int o = 16; o; o >>= 1) q += __shfl_xor_sync(0xffffffffu, q, o);
    float inv = sc[ch] / sqrtf(q);
    for (int i = lane; i < sz; i += 32) out[(size_t)ch*sz + i] = (src[i]-mean)*inv;
}

__global__ void k_wien1(){
    int tid = blockIdx.x*256 + threadIdx.x;
    if (tid >= 24*HP*5) return;
    int o = tid / (HP*5);
    int r = tid - o*HP*5;
    int u = r / 5, w = r - u*5;
    float ax = 0.f, ay = 0.f;
    for (int h = 0; h < 5; ++h){
        int rr = (h >= 2) ? (h - 2) : (h + 268);
        float2 t = g_tw[(u*rr) % HP];
        float v = g_ww[o*25 + h*5 + w];
        ax += v*t.x; ay += v*t.y;
    }
    g_tempG[tid] = make_float2(ax, ay);
}

__global__ void k_S(){
    int p = blockIdx.x*256 + threadIdx.x;
    if (p >= NPIX) return;
    int u = p / HP, v = p - u*HP;
    float2 tws[5];
    #pragma unroll
    for (int w = 0; w < 5; ++w){
        int rr = (w >= 2) ? (w - 2) : (w + 268);
        tws[w] = g_tw[(v*rr) % HP];
    }
    float s = 0.f;
    for (int o = 0; o < 24; ++o){
        float ax = 0.f, ay = 0.f;
        int base = (o*HP + u)*5;
        #pragma unroll
        for (int w = 0; w < 5; ++w){
            float2 g = g_tempG[base + w];
            float2 t = tws[w];
            ax += g.x*t.x - g.y*t.y;
            ay += g.x*t.y + g.y*t.x;
        }
        s += ax*ax + ay*ay;
    }
    g_S[p] = s;
}

__global__ void k_dft_rows_real(const float* __restrict__ in, float2* __restrict__ out){
    __shared__ float  sv[HP];
    __shared__ float2 stw[HP];
    int plane = blockIdx.y, row = blockIdx.x;
    const float* src = in + (size_t)plane*NPIX + (size_t)row*HP;
    for (int i = threadIdx.x; i < HP; i += blockDim.x){ sv[i] = src[i]; stw[i] = g_tw[i]; }
    __syncthreads();
    int k = threadIdx.x;
    if (k < HP){
        float ax = 0.f, ay = 0.f; int idx = 0;
        for (int c = 0; c < HP; ++c){
            float2 t = stw[idx]; float s = sv[c];
            ax = fmaf(s, t.x, ax);
            ay = fmaf(s, t.y, ay);
            idx += k; if (idx >= HP) idx -= HP;
        }
        out[(size_t)plane*NPIX + (size_t)row*HP + k] = make_float2(ax, ay);
    }
}

__global__ void k_dft_rows_c(const float2* __restrict__ in, float2* __restrict__ out,
                             float sgn, float scale){
    __shared__ float2 sv[HP];
    __shared__ float2 stw[HP];
    int plane = blockIdx.y, row = blockIdx.x;
    const float2* src = in + (size_t)plane*NPIX + (size_t)row*HP;
    for (int i = threadIdx.x; i < HP; i += blockDim.x){
        sv[i] = src[i];
        float2 t = g_tw[i]; stw[i] = make_float2(t.x, t.y*sgn);
    }
    __syncthreads();
    int k = threadIdx.x;
    if (k < HP){
        float ax = 0.f, ay = 0.f; int idx = 0;
        for (int c = 0; c < HP; ++c){
            float2 t = stw[idx]; float2 s = sv[c];
            ax = fmaf(s.x, t.x, fmaf(-s.y, t.y, ax));
            ay = fmaf(s.x, t.y, fmaf( s.y, t.x, ay));
            idx += k; if (idx >= HP) idx -= HP;
        }
        out[(size_t)plane*NPIX + (size_t)row*HP + k] = make_float2(ax*scale, ay*scale);
    }
}

__global__ void k_dft_cols_c(const float2* __restrict__ in, float2* __restrict__ out,
                             float sgn, float scale){
    __shared__ float2 sv[HP];
    __shared__ float2 stw[HP];
    int plane = blockIdx.y, col = blockIdx.x;
    const float2* src = in + (size_t)plane*NPIX + col;
    for (int i = threadIdx.x; i < HP; i += blockDim.x){
        sv[i] = src[(size_t)i*HP];
        float2 t = g_tw[i]; stw[i] = make_float2(t.x, t.y*sgn);
    }
    __syncthreads();
    int k = threadIdx.x;
    if (k < HP){
        float ax = 0.f, ay = 0.f; int idx = 0;
        for (int c = 0; c < HP; ++c){
            float2 t = stw[idx]; float2 s = sv[c];
            ax = fmaf(s.x, t.x, fmaf(-s.y, t.y, ax));
            ay = fmaf(s.x, t.y, fmaf( s.y, t.x, ay));
            idx += k; if (idx >= HP) idx -= HP;
        }
        out[(size_t)plane*NPIX + (size_t)k*HP + col] = make_float2(ax*scale, ay*scale);
    }
}

__global__ void k_dft_cols_real(const float2* __restrict__ in, float* __restrict__ out,
                                float sgn, float scale){
    __shared__ float2 sv[HP];
    __shared__ float2 stw[HP];
    int plane = blockIdx.y, col = blockIdx.x;
    const float2* src = in + (size_t)plane*NPIX + col;
    for (int i = threadIdx.x; i < HP; i += blockDim.x){
        sv[i] = src[(size_t)i*HP];
        float2 t = g_tw[i]; stw[i] = make_float2(t.x, t.y*sgn);
    }
    __syncthreads();
    int k = threadIdx.x;
    if (k < HP){
        float ax = 0.f; int idx = 0;
        for (int c = 0; c < HP; ++c){
            float2 t = stw[idx]; float2 s = sv[c];
            ax = fmaf(s.x, t.x, fmaf(-s.y, t.y, ax));
            idx += k; if (idx >= HP) idx -= HP;
        }
        out[(size_t)plane*NPIX + (size_t)k*HP + col] = ax*scale;
    }
}

__global__ void k_etprod(){
    int p = blockIdx.x*256 + threadIdx.x;
    if (p >= NPIX) return;
    int b = blockIdx.y;
    float2 X = g_X[(size_t)b*NPIX + p];
    float2 H = g_Hf[p];
    g_T2[(size_t)b*NPIX + p] = make_float2(X.x*H.x - X.y*H.y, X.x*H.y + X.y*H.x);
}

__global__ void k_etapply(){
    int p = blockIdx.x*256 + threadIdx.x;
    if (p >= NPIX) return;
    int b = blockIdx.y;
    int y = p / HP, x = p - y*HP;
    float a = g_ah[y]*g_aw[x];
    float v = g_xp[(size_t)b*NPIX + p];
    g_xp[(size_t)b*NPIX + p] = a*v + (1.f - a)*g_z[(size_t)b*NPIX + p];
}

__global__ void k_amp(const float* __restrict__ alpha){
    __shared__ float red[256];
    int d = blockIdx.x;
    float ad = expf(alpha[d]);
    float s = 0.f;
    for (int p = threadIdx.x; p < NPIX; p += 256){
        float2 H = g_Hf[p];
        float h2 = H.x*H.x + H.y*H.y;
        float den = h2 + ad*g_S[p];
        s += h2 / (den*den);
    }
    red[threadIdx.x] = s; __syncthreads();
    for (int o = 128; o; o >>= 1){
        if (threadIdx.x < o) red[threadIdx.x] += red[threadIdx.x + o];
        __syncthreads();
    }
    if (threadIdx.x == 0) g_amp[d] = red[0] / (float)NPIX;
}

__global__ void k_cstdn(const float* __restrict__ stdn){
    int n = threadIdx.x;
    if (n < ND){
        int b = n >> 2, d = n & 3;
        g_cstdn[n] = sqrtf(stdn[b]*stdn[b]*g_amp[d]);
    }
}

__global__ void k_wprod(const float* __restrict__ alpha){
    int p = blockIdx.x*256 + threadIdx.x;
    if (p >= NPIX) return;
    int n = blockIdx.y;
    int b = n >> 2, d = n & 3;
    float2 H = g_Hf[p];
    float ad = expf(alpha[d]);
    float den = H.x*H.x + H.y*H.y + ad*g_S[p];
    float Tx =  H.x/den;
    float Ty = -H.y/den;
    float2 Y = g_X[(size_t)b*NPIX + p];
    g_T2[(size_t)n*NPIX + p] = make_float2(Tx*Y.x - Ty*Y.y, Tx*Y.y + Ty*Y.x);
}

__global__ __launch_bounds__(256) void k_conv1(const float* __restrict__ bias){
    __shared__ float s_in[20*20];
    __shared__ float s_w[32*25];
    int n = blockIdx.z;
    int ty = threadIdx.y, tx = threadIdx.x;
    int tid = ty*16 + tx;
    int y0 = blockIdx.y*16 - 2, x0 = blockIdx.x*16 - 2;
    const float* src = g_z + (size_t)n*NPIX;
    for (int i = tid; i < 400; i += 256){
        int r = i / 20, c = i - r*20;
        s_in[i] = src[refl(y0+r,HP)*HP + refl(x0+c,HP)];
    }
    for (int i = tid; i < 800; i += 256) s_w[i] = g_cw[i];
    __syncthreads();
    float acc[32];
    #pragma unroll
    for (int o = 0; o < 32; ++o) acc[o] = bias[o];
    #pragma unroll
    for (int ky = 0; ky < 5; ++ky)
        #pragma unroll
        for (int kx = 0; kx < 5; ++kx){
            float v = s_in[(ty+ky)*20 + tx + kx];
            #pragma unroll
            for (int o = 0; o < 32; ++o) acc[o] = fmaf(v, s_w[o*25 + ky*5 + kx], acc[o]);
        }
    int oy = blockIdx.y*16 + ty, ox = blockIdx.x*16 + tx;
    if (oy < HP && ox < HP){
        #pragma unroll
        for (int o = 0; o < 32; ++o)
            g_f0[((size_t)n*32 + o)*NPIX + oy*HP + ox] = acc[o];
    }
}

template<int CIN>
__global__ __launch_bounds__(256,2) void k_conv3x3(
    const float* __restrict__ in, const float* __restrict__ w,
    const float* __restrict__ bias, const float* __restrict__ prelu,
    const float* __restrict__ skip, float* __restrict__ out, int nOcg)
{
    __shared__ float s_in[34*34];
    __shared__ float s_w[8*CIN*9];
    int n   = blockIdx.z / nOcg;
    int ocg = blockIdx.z % nOcg;
    int ty = threadIdx.y, tx = threadIdx.x;
    int tid = ty*16 + tx;
    int y0 = blockIdx.y*32 - 1, x0 = blockIdx.x*32 - 1;
    int cout = nOcg*8;

    const float* wbase = w + (size_t)ocg*8*CIN*9;
    for (int i = tid; i < 8*CIN*9; i += 256) s_w[i] = wbase[i];

    float acc[8][4];
    #pragma unroll
    for (int o = 0; o < 8; ++o){
        float bb = bias[ocg*8 + o];
        acc[o][0]=bb; acc[o][1]=bb; acc[o][2]=bb; acc[o][3]=bb;
    }

    const float* inbase = in + (size_t)n*CIN*NPIX;
    for (int cin = 0; cin < CIN; ++cin){
        __syncthreads();
        const float* src = inbase + (size_t)cin*NPIX;
        float slope = prelu[cin];
        for (int i = tid; i < 34*34; i += 256){
            int r = i / 34, c = i - r*34;
            float v = src[refl(y0+r,HP)*HP + refl(x0+c,HP)];
            s_in[i] = (v >= 0.f) ? v : v*slope;
        }
        __syncthreads();
        float p[4][4];
        #pragma unroll
        for (int r = 0; r < 4; ++r)
            #pragma unroll
            for (int c = 0; c < 4; ++c)
                p[r][c] = s_in[(2*ty + r)*34 + 2*tx + c];
        #pragma unroll
        for (int o = 0; o < 8; ++o){
            const float* ws = &s_w[(o*CIN + cin)*9];
            float w0=ws[0],w1=ws[1],w2=ws[2],w3=ws[3],w4=ws[4],w5=ws[5],w6=ws[6],w7=ws[7],w8=ws[8];
            #pragma unroll
            for (int py = 0; py < 2; ++py)
                #pragma unroll
                for (int px = 0; px < 2; ++px){
                    float a = acc[o][py*2+px];
                    a = fmaf(p[py+0][px+0],w0,a); a = fmaf(p[py+0][px+1],w1,a); a = fmaf(p[py+0][px+2],w2,a);
                    a = fmaf(p[py+1][px+0],w3,a); a = fmaf(p[py+1][px+1],w4,a); a = fmaf(p[py+1][px+2],w5,a);
                    a = fmaf(p[py+2][px+0],w6,a); a = fmaf(p[py+2][px+1],w7,a); a = fmaf(p[py+2][px+2],w8,a);
                    acc[o][py*2+px] = a;
                }
        }
    }
    #pragma unroll
    for (int o = 0; o < 8; ++o){
        int oc = ocg*8 + o;
        size_t plane = ((size_t)n*cout + oc)*NPIX;
        #pragma unroll
        for (int py = 0; py < 2; ++py){
            int oy = y0 + 1 + 2*ty + py;
            if (oy < HP){
                #pragma unroll
                for (int px = 0; px < 2; ++px){
                    int ox = x0 + 1 + 2*tx + px;
                    if (ox < HP){
                        float v = acc[o][py*2+px];
                        if (skip) v += skip[plane + (size_t)oy*HP + ox];
                        out[plane + (size_t)oy*HP + ox] = v;
                    }
                }
            }
        }
    }
}

__global__ __launch_bounds__(256) void k_convT(const float* __restrict__ in,
                                               const float* __restrict__ biasT){
    __shared__ float s_in[20*20];
    __shared__ float s_w[25];
    int n = blockIdx.z;
    int ty = threadIdx.y, tx = threadIdx.x;
    int tid = ty*16 + tx;
    int y0 = blockIdx.y*16, x0 = blockIdx.x*16;
    float acc = biasT[0];
    for (int oc = 0; oc < 32; ++oc){
        __syncthreads();
        const float* src = in + ((size_t)n*32 + oc)*NPIX;
        for (int i = tid; i < 400; i += 256){
            int r = i / 20, c = i - r*20;
            int yy = y0 - 2 + r, xx = x0 - 2 + c;
            s_in[i] = (yy >= 0 && yy < HP && xx >= 0 && xx < HP) ? src[yy*HP + xx] : 0.f;
        }
        if (tid < 25) s_w[tid] = g_cw[oc*25 + tid];
        __syncthreads();
        #pragma unroll
        for (int u = 0; u < 5; ++u)
            #pragma unroll
            for (int v = 0; v < 5; ++v)
                acc = fmaf(s_in[(ty + 4 - u)*20 + tx + 4 - v], s_w[u*5 + v], acc);
    }
    int oy = y0 + ty, ox = x0 + tx;
    if (oy < HP && ox < HP) g_ct[(size_t)n*NPIX + oy*HP + ox] = acc;
}

__global__ void k_nrm(){
    __shared__ float red[256];
    int n = blockIdx.x;
    float s = 0.f;
    for (int p = threadIdx.x; p < NPIX; p += 256){
        float v = g_ct[(size_t)n*NPIX + p];
        s += v*v;
    }
    red[threadIdx.x] = s; __syncthreads();
    for (int o = 128; o; o >>= 1){
        if (threadIdx.x < o) red[threadIdx.x] += red[threadIdx.x + o];
        __syncthreads();
    }
    if (threadIdx.x == 0) g_nrm2[n] = red[0];
}

__global__ void k_scl(const float* __restrict__ ap){
    int n = threadIdx.x;
    if (n < ND){
        float eps = expf(ap[0]) * g_cstdn[n] * sqrtf((float)(NPIX - 1));
        float nr  = sqrtf(g_nrm2[n]);
        g_scl[n] = (nr > eps) ? eps / fmaxf(nr, 1e-12f) : 1.f;
    }
}

__global__ void k_final(const float* __restrict__ mw, float* __restrict__ outp){
    int b = blockIdx.y;
    int p = blockIdx.x*256 + threadIdx.x;
    int y = p >> 8, x = p & 255;
    size_t q = (size_t)(y + 7)*HP + (x + 7);
    float acc = 0.f;
    #pragma unroll
    for (int d = 0; d < 4; ++d){
        int n = b*4 + d;
        float r = g_z[(size_t)n*NPIX + q] - g_ct[(size_t)n*NPIX + q]*g_scl[n];
        r = fminf(fmaxf(r, 0.f), 255.f);
        acc += mw[d]*r;
    }
    outp[(size_t)b*65536 + p] = acc;
}

extern "C" void kernel_launch(void* const* d_in, const int* in_sizes, int n_in,
                              void* d_out, int out_size){
    const float* x      = (const float*)d_in[0];
    const float* bk     = (const float*)d_in[1];
    const float* stdn   = (const float*)d_in[2];
    const float* wienw  = (const float*)d_in[3];
    const float* wiensc = (const float*)d_in[4];
    const float* alpha  = (const float*)d_in[5];
    const float* convw  = (const float*)d_in[6];
    const float* scalef = (const float*)d_in[7];
    const float* biasf  = (const float*)d_in[8];
    const float* biast  = (const float*)d_in[9];
    const float* p1     = (const float*)d_in[10];
    const float* w1     = (const float*)d_in[11];
    const float* s1     = (const float*)d_in[12];
    const float* b1     = (const float*)d_in[13];
    const float* p2     = (const float*)d_in[14];
    const float* w2     = (const float*)d_in[15];
    const float* s2     = (const float*)d_in[16];
    const float* b2     = (const float*)d_in[17];
    const float* aproj  = (const float*)d_in[18];
    const float* mw     = (const float*)d_in[19];
    float* outp = (float*)d_out;

    float *pxp, *pz, *pww, *pcw, *pw1, *pw2, *pf0, *pf1;
    float2 *pX, *pT1, *pT2;
    cudaGetSymbolAddress((void**)&pxp, g_xp);
    cudaGetSymbolAddress((void**)&pz,  g_z);
    cudaGetSymbolAddress((void**)&pww, g_ww);
    cudaGetSymbolAddress((void**)&pcw, g_cw);
    cudaGetSymbolAddress((void**)&pw1, g_w1);
    cudaGetSymbolAddress((void**)&pw2, g_w2);
    cudaGetSymbolAddress((void**)&pf0, g_f0);
    cudaGetSymbolAddress((void**)&pf1, g_f1);
    cudaGetSymbolAddress((void**)&pX,  g_X);
    cudaGetSymbolAddress((void**)&pT1, g_T1);
    cudaGetSymbolAddress((void**)&pT2, g_T2);

    const int PB = (NPIX + 255)/256;
    const float INV = 1.0f/(float)HP;

    k_init_tw<<<1, 288>>>();
    k_wnorm<<<24, 32>>>(wienw, wiensc, pww, 25);
    k_wnorm<<<32, 32>>>(convw, scalef, pcw, 25);
    k_wnorm<<<320, 32>>>(w1, s1, pw1, 288);
    k_wnorm<<<160, 32>>>(w2, s2, pw2, 576);

    k_pad<<<dim3(PB, NB), 256>>>(x);
    k_alphas<<<1, 288>>>(bk);
    k_psf1<<<(HP*15 + 255)/256, 256>>>(bk);
    k_psf2<<<PB, 256>>>();
    k_wien1<<<(24*HP*5 + 255)/256, 256>>>();
    k_S<<<PB, 256>>>();

    // fft2(xp) -> X  (2 planes)
    k_dft_rows_real<<<dim3(HP, NB), 288>>>(pxp, pT1);
    k_dft_cols_c   <<<dim3(HP, NB), 288>>>(pT1, pX, 1.f, 1.f);
    // blurred = ifft2(X * Hf).real
    k_etprod<<<dim3(PB, NB), 256>>>();
    k_dft_rows_c   <<<dim3(HP, NB), 288>>>(pT2, pT1, -1.f, INV);
    k_dft_cols_real<<<dim3(HP, NB), 288>>>(pT1, pz, -1.f, INV);
    k_etapply<<<dim3(PB, NB), 256>>>();

    // Y = fft2(xp) -> X
    k_dft_rows_real<<<dim3(HP, NB), 288>>>(pxp, pT1);
    k_dft_cols_c   <<<dim3(HP, NB), 288>>>(pT1, pX, 1.f, 1.f);

    k_amp<<<4, 256>>>(alpha);
    k_cstdn<<<1, 32>>>(stdn);

    // z = ifft2(T * Y).real  (8 planes)
    k_wprod<<<dim3(PB, ND), 256>>>(alpha);
    k_dft_rows_c   <<<dim3(HP, ND), 288>>>(pT2, pT1, -1.f, INV);
    k_dft_cols_real<<<dim3(HP, ND), 288>>>(pT1, pz, -1.f, INV);

    // CNN
    k_conv1<<<dim3(17,17,ND), dim3(16,16)>>>(biasf);
    for (int i = 0; i < 5; ++i){
        k_conv3x3<32><<<dim3(9,9,ND*8), dim3(16,16)>>>(
            pf0, pw1 + (size_t)i*64*32*9, b1 + i*64, p1 + i*32, nullptr, pf1, 8);
        k_conv3x3<64><<<dim3(9,9,ND*4), dim3(16,16)>>>(
            pf1, pw2 + (size_t)i*32*64*9, b2 + i*32, p2 + i*64,
            (i == 0) ? pf0 : nullptr, pf0, 4);
    }
    k_convT<<<dim3(17,17,ND), dim3(16,16)>>>(pf0, biast);

    k_nrm<<<ND, 256>>>();
    k_scl<<<1, 32>>>(aproj);
    k_final<<<dim3(256, NB), 256>>>(mw, outp);
}

// round 4
// speedup vs baseline: 1.3024x; 1.3024x over previous
#include <cuda_runtime.h>
#include <math.h>

#define HP   270
#define NPIX 72900
#define NB   2
#define ND   8
#define HIN  256

typedef unsigned long long u64;

__device__ float  g_xp[NB*NPIX];
__device__ float2 g_X [NB*NPIX];
__device__ float2 g_T1[ND*NPIX];
__device__ float2 g_T2[ND*NPIX];
__device__ float2 g_Hf[NPIX];
__device__ float  g_S [NPIX];
__device__ float2 g_tw[HP];
__device__ float2 g_tempB[HP*15];
__device__ float2 g_tempG[24*HP*5];
__device__ float  g_ah[HP];
__device__ float  g_aw[HP];
__device__ float  g_z [ND*NPIX];
__device__ float  g_ww[24*25];
__device__ float  g_cw[32*25];
__device__ float  g_w1[5*64*32*9];
__device__ float  g_w2[5*32*64*9];
__device__ float  g_f0[ND*32*NPIX];
__device__ float  g_f1[ND*64*NPIX];
__device__ float  g_ct[ND*NPIX];
__device__ float  g_amp[4];
__device__ float  g_cstdn[ND];
__device__ float  g_nrm2[ND];
__device__ float  g_scl[ND];

static __device__ __forceinline__ int refl(int i, int n){
    if (i < 0)  i = -i - 1;
    if (i >= n) i = 2*n - 1 - i;
    return i;
}

static __device__ __forceinline__ u64 pack2(float lo, float hi){
    u64 r;
    asm("mov.b64 %0, {%1, %2};" : "=l"(r) : "f"(lo), "f"(hi));
    return r;
}
static __device__ __forceinline__ u64 ffma2(u64 a, u64 b, u64 c){
    u64 d;
    asm("fma.rn.f32x2 %0, %1, %2, %3;" : "=l"(d) : "l"(a), "l"(b), "l"(c));
    return d;
}
static __device__ __forceinline__ float2 unpack2(u64 v){
    float lo, hi;
    asm("mov.b64 {%0, %1}, %2;" : "=f"(lo), "=f"(hi) : "l"(v));
    return make_float2(lo, hi);
}

__global__ void k_init_tw(){
    int t = threadIdx.x;
    if (t < HP){
        double ang = -2.0 * 3.14159265358979323846 * (double)t / (double)HP;
        double s, c; sincos(ang, &s, &c);
        g_tw[t] = make_float2((float)c, (float)s);
    }
}

__global__ void k_pad(const float* __restrict__ x){
    int p = blockIdx.x*256 + threadIdx.x;
    if (p >= NPIX) return;
    int b = blockIdx.y;
    int y = p / HP, xx = p - y*HP;
    g_xp[b*NPIX + p] = x[b*HIN*HIN + refl(y-7,HIN)*HIN + refl(xx-7,HIN)];
}

__global__ void k_alphas(const float* __restrict__ bk){
    __shared__ float ph[15], pw[15], rh[15], rw[15];
    int t = threadIdx.x;
    if (t < 15){
        float s = 0.f, q = 0.f;
        for (int j = 0; j < 15; ++j){ s += bk[t*15+j]; q += bk[j*15+t]; }
        ph[t] = s; pw[t] = q;
    }
    __syncthreads();
    if (t < 15){
        float s = 0.f, q = 0.f;
        for (int j = 0; j + t < 15; ++j){ s += ph[j]*ph[j+t]; q += pw[j]*pw[j+t]; }
        rh[t] = s; rw[t] = q;
    }
    __syncthreads();
    if (t < HP){
        float zh = 0.f, zw = 0.f;
        if (t <= 14)       { zh = rh[t];       zw = rw[t];       }
        else if (t >= 255) { zh = rh[269 - t]; zw = rw[269 - t]; }
        g_ah[t] = 1.f - zh / rh[0];
        g_aw[t] = 1.f - zw / rw[0];
    }
}

__global__ void k_psf1(const float* __restrict__ bk){
    int tid = blockIdx.x*256 + threadIdx.x;
    if (tid >= HP*15) return;
    int u = tid / 15, w = tid - u*15;
    float ax = 0.f, ay = 0.f;
    for (int h = 0; h < 15; ++h){
        int rr = (h >= 7) ? (h - 7) : (h + 263);
        float2 t = g_tw[(u*rr) % HP];
        float v = bk[h*15 + w];
        ax += v*t.x; ay += v*t.y;
    }
    g_tempB[tid] = make_float2(ax, ay);
}

__global__ void k_psf2(){
    int p = blockIdx.x*256 + threadIdx.x;
    if (p >= NPIX) return;
    int u = p / HP, v = p - u*HP;
    float ax = 0.f, ay = 0.f;
    for (int w = 0; w < 15; ++w){
        int rr = (w >= 7) ? (w - 7) : (w + 263);
        float2 t = g_tw[(v*rr) % HP];
        float2 b = g_tempB[u*15 + w];
        ax += b.x*t.x - b.y*t.y;
        ay += b.x*t.y + b.y*t.x;
    }
    g_Hf[p] = make_float2(ax, ay);
}

__global__ void k_wnorm(const float* __restrict__ w, const float* __restrict__ sc,
                        float* __restrict__ out, int sz){
    int ch = blockIdx.x;
    const float* src = w + (size_t)ch*sz;
    int lane = threadIdx.x;
    float s = 0.f;
    for (int i = lane; i < sz; i += 32) s += src[i];
    #pragma unroll
    for (int o = 16; o; o >>= 1) s += __shfl_xor_sync(0xffffffffu, s, o);
    float mean = s / (float)sz;
    float q = 0.f;
    for (int i = lane; i < sz; i += 32){ float v = src[i]-mean; q += v*v; }
    #pragma unroll
    for (int o = 16; o; o >>= 1) q += __shfl_xor_sync(0xffffffffu, q, o);
    float inv = sc[ch] / sqrtf(q);
    for (int i = lane; i < sz; i += 32) out[(size_t)ch*sz + i] = (src[i]-mean)*inv;
}

__global__ void k_wien1(){
    int tid = blockIdx.x*256 + threadIdx.x;
    if (tid >= 24*HP*5) return;
    int o = tid / (HP*5);
    int r = tid - o*HP*5;
    int u = r / 5, w = r - u*5;
    float ax = 0.f, ay = 0.f;
    for (int h = 0; h < 5; ++h){
        int rr = (h >= 2) ? (h - 2) : (h + 268);
        float2 t = g_tw[(u*rr) % HP];
        float v = g_ww[o*25 + h*5 + w];
        ax += v*t.x; ay += v*t.y;
    }
    g_tempG[tid] = make_float2(ax, ay);
}

__global__ void k_S(){
    int p = blockIdx.x*256 + threadIdx.x;
    if (p >= NPIX) return;
    int u = p / HP, v = p - u*HP;
    float2 tws[5];
    #pragma unroll
    for (int w = 0; w < 5; ++w){
        int rr = (w >= 2) ? (w - 2) : (w + 268);
        tws[w] = g_tw[(v*rr) % HP];
    }
    float s = 0.f;
    for (int o = 0; o < 24; ++o){
        float ax = 0.f, ay = 0.f;
        int base = (o*HP + u)*5;
        #pragma unroll
        for (int w = 0; w < 5; ++w){
            float2 g = g_tempG[base + w];
            float2 t = tws[w];
            ax += g.x*t.x - g.y*t.y;
            ay += g.x*t.y + g.y*t.x;
        }
        s += ax*ax + ay*ay;
    }
    g_S[p] = s;
}

__global__ void k_dft_rows_real(const float* __restrict__ in, float2* __restrict__ out){
    __shared__ float sv[HP];
    __shared__ __align__(8) u64 sT[HP];   // (tx, ty)
    int plane = blockIdx.y, row = blockIdx.x;
    const float* src = in + (size_t)plane*NPIX + (size_t)row*HP;
    for (int i = threadIdx.x; i < HP; i += blockDim.x){
        sv[i] = src[i];
        float2 t = g_tw[i];
        sT[i] = pack2(t.x, t.y);
    }
    __syncthreads();
    int k = threadIdx.x;
    if (k < HP){
        u64 acc = 0; int idx = 0;
        #pragma unroll 5
        for (int c = 0; c < HP; ++c){
            float s = sv[c];
            acc = ffma2(pack2(s, s), sT[idx], acc);
            idx += k; if (idx >= HP) idx -= HP;
        }
        float2 a = unpack2(acc);
        out[(size_t)plane*NPIX + (size_t)row*HP + k] = a;
    }
}

__global__ void k_dft_rows_c(const float2* __restrict__ in, float2* __restrict__ out,
                             float sgn, float scale){
    __shared__ __align__(8) float2 sv[HP];
    __shared__ __align__(8) u64 sTA[HP], sTB[HP];
    int plane = blockIdx.y, row = blockIdx.x;
    const float2* src = in + (size_t)plane*NPIX + (size_t)row*HP;
    for (int i = threadIdx.x; i < HP; i += blockDim.x){
        sv[i] = src[i];
        float2 t = g_tw[i];
        float ty = sgn*t.y;
        sTA[i] = pack2(t.x, t.x);
        sTB[i] = pack2(ty, ty);
    }
    __syncthreads();
    int k = threadIdx.x;
    if (k < HP){
        const u64* sv64 = (const u64*)sv;
        u64 P = 0, Q = 0; int idx = 0;
        #pragma unroll 5
        for (int c = 0; c < HP; ++c){
            u64 s = sv64[c];
            P = ffma2(s, sTA[idx], P);
            Q = ffma2(s, sTB[idx], Q);
            idx += k; if (idx >= HP) idx -= HP;
        }
        float2 p = unpack2(P), q = unpack2(Q);
        out[(size_t)plane*NPIX + (size_t)row*HP + k] =
            make_float2((p.x - q.y)*scale, (p.y + q.x)*scale);
    }
}

__global__ void k_dft_cols_c(const float2* __restrict__ in, float2* __restrict__ out,
                             float sgn, float scale){
    __shared__ __align__(8) float2 sv[HP];
    __shared__ __align__(8) u64 sTA[HP], sTB[HP];
    int plane = blockIdx.y, col = blockIdx.x;
    const float2* src = in + (size_t)plane*NPIX + col;
    for (int i = threadIdx.x; i < HP; i += blockDim.x){
        sv[i] = src[(size_t)i*HP];
        float2 t = g_tw[i];
        float ty = sgn*t.y;
        sTA[i] = pack2(t.x, t.x);
        sTB[i] = pack2(ty, ty);
    }
    __syncthreads();
    int k = threadIdx.x;
    if (k < HP){
        const u64* sv64 = (const u64*)sv;
        u64 P = 0, Q = 0; int idx = 0;
        #pragma unroll 5
        for (int c = 0; c < HP; ++c){
            u64 s = sv64[c];
            P = ffma2(s, sTA[idx], P);
            Q = ffma2(s, sTB[idx], Q);
            idx += k; if (idx >= HP) idx -= HP;
        }
        float2 p = unpack2(P), q = unpack2(Q);
        out[(size_t)plane*NPIX + (size_t)k*HP + col] =
            make_float2((p.x - q.y)*scale, (p.y + q.x)*scale);
    }
}

// real(ifft col pass): ax = sum sx*tx - sy*sgn*ty = dot(s, (tx, -sgn*ty))
__global__ void k_dft_cols_real(const float2* __restrict__ in, float* __restrict__ out,
                                float sgn, float scale){
    __shared__ __align__(8) float2 sv[HP];
    __shared__ __align__(8) u64 sC[HP];
    int plane = blockIdx.y, col = blockIdx.x;
    const float2* src = in + (size_t)plane*NPIX + col;
    for (int i = threadIdx.x; i < HP; i += blockDim.x){
        sv[i] = src[(size_t)i*HP];
        float2 t = g_tw[i];
        sC[i] = pack2(t.x, -sgn*t.y);
    }
    __syncthreads();
    int k = threadIdx.x;
    if (k < HP){
        const u64* sv64 = (const u64*)sv;
        u64 acc = 0; int idx = 0;
        #pragma unroll 5
        for (int c = 0; c < HP; ++c){
            acc = ffma2(sv64[c], sC[idx], acc);
            idx += k; if (idx >= HP) idx -= HP;
        }
        float2 a = unpack2(acc);
        out[(size_t)plane*NPIX + (size_t)k*HP + col] = (a.x + a.y)*scale;
    }
}

__global__ void k_etprod(){
    int p = blockIdx.x*256 + threadIdx.x;
    if (p >= NPIX) return;
    int b = blockIdx.y;
    float2 X = g_X[(size_t)b*NPIX + p];
    float2 H = g_Hf[p];
    g_T2[(size_t)b*NPIX + p] = make_float2(X.x*H.x - X.y*H.y, X.x*H.y + X.y*H.x);
}

__global__ void k_etapply(){
    int p = blockIdx.x*256 + threadIdx.x;
    if (p >= NPIX) return;
    int b = blockIdx.y;
    int y = p / HP, x = p - y*HP;
    float a = g_ah[y]*g_aw[x];
    float v = g_xp[(size_t)b*NPIX + p];
    g_xp[(size_t)b*NPIX + p] = a*v + (1.f - a)*g_z[(size_t)b*NPIX + p];
}

__global__ void k_amp(const float* __restrict__ alpha){
    __shared__ float red[256];
    int d = blockIdx.x;
    float ad = expf(alpha[d]);
    float s = 0.f;
    for (int p = threadIdx.x; p < NPIX; p += 256){
        float2 H = g_Hf[p];
        float h2 = H.x*H.x + H.y*H.y;
        float den = h2 + ad*g_S[p];
        s += h2 / (den*den);
    }
    red[threadIdx.x] = s; __syncthreads();
    for (int o = 128; o; o >>= 1){
        if (threadIdx.x < o) red[threadIdx.x] += red[threadIdx.x + o];
        __syncthreads();
    }
    if (threadIdx.x == 0) g_amp[d] = red[0] / (float)NPIX;
}

__global__ void k_cstdn(const float* __restrict__ stdn){
    int n = threadIdx.x;
    if (n < ND){
        int b = n >> 2, d = n & 3;
        g_cstdn[n] = sqrtf(stdn[b]*stdn[b]*g_amp[d]);
    }
}

__global__ void k_wprod(const float* __restrict__ alpha){
    int p = blockIdx.x*256 + threadIdx.x;
    if (p >= NPIX) return;
    int n = blockIdx.y;
    int b = n >> 2, d = n & 3;
    float2 H = g_Hf[p];
    float ad = expf(alpha[d]);
    float den = H.x*H.x + H.y*H.y + ad*g_S[p];
    float Tx =  H.x/den;
    float Ty = -H.y/den;
    float2 Y = g_X[(size_t)b*NPIX + p];
    g_T2[(size_t)n*NPIX + p] = make_float2(Tx*Y.x - Ty*Y.y, Tx*Y.y + Ty*Y.x);
}

__global__ __launch_bounds__(256) void k_conv1(const float* __restrict__ bias){
    __shared__ float s_in[20*20];
    __shared__ float s_w[32*25];
    int n = blockIdx.z;
    int ty = threadIdx.y, tx = threadIdx.x;
    int tid = ty*16 + tx;
    int y0 = blockIdx.y*16 - 2, x0 = blockIdx.x*16 - 2;
    const float* src = g_z + (size_t)n*NPIX;
    for (int i = tid; i < 400; i += 256){
        int r = i / 20, c = i - r*20;
        s_in[i] = src[refl(y0+r,HP)*HP + refl(x0+c,HP)];
    }
    for (int i = tid; i < 800; i += 256) s_w[i] = g_cw[i];
    __syncthreads();
    float acc[32];
    #pragma unroll
    for (int o = 0; o < 32; ++o) acc[o] = bias[o];
    #pragma unroll
    for (int ky = 0; ky < 5; ++ky)
        #pragma unroll
        for (int kx = 0; kx < 5; ++kx){
            float v = s_in[(ty+ky)*20 + tx + kx];
            #pragma unroll
            for (int o = 0; o < 32; ++o) acc[o] = fmaf(v, s_w[o*25 + ky*5 + kx], acc[o]);
        }
    int oy = blockIdx.y*16 + ty, ox = blockIdx.x*16 + tx;
    if (oy < HP && ox < HP){
        #pragma unroll
        for (int o = 0; o < 32; ++o)
            g_f0[((size_t)n*32 + o)*NPIX + oy*HP + ox] = acc[o];
    }
}

// FFMA2 conv: 32x32 tile, 8 oc/block as 4 oc-pairs, 2x2 px/thread, 4-cin staging.
template<int CIN>
__global__ __launch_bounds__(256,2) void k_conv3x3(
    const float* __restrict__ in, const float* __restrict__ w,
    const float* __restrict__ bias, const float* __restrict__ prelu,
    const float* __restrict__ skip, float* __restrict__ out, int nOcg)
{
    __shared__ __align__(16) float s_in[4][34*34];
    __shared__ __align__(8)  float s_w[CIN*72];      // [cin][tap(9)][oc(8)]
    int n   = blockIdx.z / nOcg;
    int ocg = blockIdx.z % nOcg;
    int ty = threadIdx.y, tx = threadIdx.x;
    int tid = ty*16 + tx;
    int y0 = blockIdx.y*32 - 1, x0 = blockIdx.x*32 - 1;
    int cout = nOcg*8;

    // transpose weights into [cin][tap][oc]
    const float* wbase = w + (size_t)ocg*8*CIN*9;
    for (int i = tid; i < CIN*72; i += 256){
        int cin = i / 72;
        int r   = i - cin*72;
        int tap = r >> 3;
        int o   = r & 7;
        s_w[i] = wbase[(o*CIN + cin)*9 + tap];
    }

    u64 acc[4][4];
    #pragma unroll
    for (int op = 0; op < 4; ++op){
        u64 bb = pack2(bias[ocg*8 + op*2], bias[ocg*8 + op*2 + 1]);
        acc[op][0]=bb; acc[op][1]=bb; acc[op][2]=bb; acc[op][3]=bb;
    }

    const float* inbase = in + (size_t)n*CIN*NPIX;
    for (int c0 = 0; c0 < CIN; c0 += 4){
        __syncthreads();
        for (int i = tid; i < 4*1156; i += 256){
            int st = i / 1156;
            int j  = i - st*1156;
            int r = j / 34, c = j - r*34;
            int cin = c0 + st;
            float v = inbase[(size_t)cin*NPIX + refl(y0+r,HP)*HP + refl(x0+c,HP)];
            float sl = prelu[cin];
            s_in[st][j] = (v >= 0.f) ? v : v*sl;
        }
        __syncthreads();
        #pragma unroll
        for (int st = 0; st < 4; ++st){
            u64 px[4][4];
            #pragma unroll
            for (int r = 0; r < 4; ++r){
                const float2* rowp = (const float2*)&s_in[st][(2*ty + r)*34 + 2*tx];
                float2 A = rowp[0], B = rowp[1];
                px[r][0] = pack2(A.x, A.x);
                px[r][1] = pack2(A.y, A.y);
                px[r][2] = pack2(B.x, B.x);
                px[r][3] = pack2(B.y, B.y);
            }
            const float* wst = &s_w[(c0+st)*72];
            #pragma unroll
            for (int ky = 0; ky < 3; ++ky)
                #pragma unroll
                for (int kx = 0; kx < 3; ++kx){
                    int tap = ky*3 + kx;
                    #pragma unroll
                    for (int op = 0; op < 4; ++op){
                        u64 wp = *(const u64*)&wst[tap*8 + op*2];
                        #pragma unroll
                        for (int py = 0; py < 2; ++py)
                            #pragma unroll
                            for (int pxi = 0; pxi < 2; ++pxi)
                                acc[op][py*2+pxi] = ffma2(px[py+ky][pxi+kx], wp, acc[op][py*2+pxi]);
                    }
                }
        }
    }

    #pragma unroll
    for (int op = 0; op < 4; ++op){
        #pragma unroll
        for (int py = 0; py < 2; ++py){
            int oy = y0 + 1 + 2*ty + py;
            if (oy >= HP) continue;
            #pragma unroll
            for (int pxi = 0; pxi < 2; ++pxi){
                int ox = x0 + 1 + 2*tx + pxi;
                if (ox >= HP) continue;
                float2 v = unpack2(acc[op][py*2+pxi]);
                int oc0 = ocg*8 + op*2;
                size_t pl0 = ((size_t)n*cout + oc0)*NPIX + (size_t)oy*HP + ox;
                size_t pl1 = pl0 + NPIX;
                float v0 = v.x, v1 = v.y;
                if (skip){ v0 += skip[pl0]; v1 += skip[pl1]; }
                out[pl0] = v0;
                out[pl1] = v1;
            }
        }
    }
}

__global__ __launch_bounds__(256) void k_convT(const float* __restrict__ in,
                                               const float* __restrict__ biasT){
    __shared__ float s_in[20*20];
    __shared__ float s_w[25];
    int n = blockIdx.z;
    int ty = threadIdx.y, tx = threadIdx.x;
    int tid = ty*16 + tx;
    int y0 = blockIdx.y*16, x0 = blockIdx.x*16;
    float acc = biasT[0];
    for (int oc = 0; oc < 32; ++oc){
        __syncthreads();
        const float* src = in + ((size_t)n*32 + oc)*NPIX;
        for (int i = tid; i < 400; i += 256){
            int r = i / 20, c = i - r*20;
            int yy = y0 - 2 + r, xx = x0 - 2 + c;
            s_in[i] = (yy >= 0 && yy < HP && xx >= 0 && xx < HP) ? src[yy*HP + xx] : 0.f;
        }
        if (tid < 25) s_w[tid] = g_cw[oc*25 + tid];
        __syncthreads();
        #pragma unroll
        for (int u = 0; u < 5; ++u)
            #pragma unroll
            for (int v = 0; v < 5; ++v)
                acc = fmaf(s_in[(ty + 4 - u)*20 + tx + 4 - v], s_w[u*5 + v], acc);
    }
    int oy = y0 + ty, ox = x0 + tx;
    if (oy < HP && ox < HP) g_ct[(size_t)n*NPIX + oy*HP + ox] = acc;
}

__global__ void k_nrm(){
    __shared__ float red[256];
    int n = blockIdx.x;
    float s = 0.f;
    for (int p = threadIdx.x; p < NPIX; p += 256){
        float v = g_ct[(size_t)n*NPIX + p];
        s += v*v;
    }
    red[threadIdx.x] = s; __syncthreads();
    for (int o = 128; o; o >>= 1){
        if (threadIdx.x < o) red[threadIdx.x] += red[threadIdx.x + o];
        __syncthreads();
    }
    if (threadIdx.x == 0) g_nrm2[n] = red[0];
}

__global__ void k_scl(const float* __restrict__ ap){
    int n = threadIdx.x;
    if (n < ND){
        float eps = expf(ap[0]) * g_cstdn[n] * sqrtf((float)(NPIX - 1));
        float nr  = sqrtf(g_nrm2[n]);
        g_scl[n] = (nr > eps) ? eps / fmaxf(nr, 1e-12f) : 1.f;
    }
}

__global__ void k_final(const float* __restrict__ mw, float* __restrict__ outp){
    int b = blockIdx.y;
    int p = blockIdx.x*256 + threadIdx.x;
    int y = p >> 8, x = p & 255;
    size_t q = (size_t)(y + 7)*HP + (x + 7);
    float acc = 0.f;
    #pragma unroll
    for (int d = 0; d < 4; ++d){
        int n = b*4 + d;
        float r = g_z[(size_t)n*NPIX + q] - g_ct[(size_t)n*NPIX + q]*g_scl[n];
        r = fminf(fmaxf(r, 0.f), 255.f);
        acc += mw[d]*r;
    }
    outp[(size_t)b*65536 + p] = acc;
}

extern "C" void kernel_launch(void* const* d_in, const int* in_sizes, int n_in,
                              void* d_out, int out_size){
    const float* x      = (const float*)d_in[0];
    const float* bk     = (const float*)d_in[1];
    const float* stdn   = (const float*)d_in[2];
    const float* wienw  = (const float*)d_in[3];
    const float* wiensc = (const float*)d_in[4];
    const float* alpha  = (const float*)d_in[5];
    const float* convw  = (const float*)d_in[6];
    const float* scalef = (const float*)d_in[7];
    const float* biasf  = (const float*)d_in[8];
    const float* biast  = (const float*)d_in[9];
    const float* p1     = (const float*)d_in[10];
    const float* w1     = (const float*)d_in[11];
    const float* s1     = (const float*)d_in[12];
    const float* b1     = (const float*)d_in[13];
    const float* p2     = (const float*)d_in[14];
    const float* w2     = (const float*)d_in[15];
    const float* s2     = (const float*)d_in[16];
    const float* b2     = (const float*)d_in[17];
    const float* aproj  = (const float*)d_in[18];
    const float* mw     = (const float*)d_in[19];
    float* outp = (float*)d_out;

    float *pxp, *pz, *pww, *pcw, *pw1, *pw2, *pf0, *pf1;
    float2 *pX, *pT1, *pT2;
    cudaGetSymbolAddress((void**)&pxp, g_xp);
    cudaGetSymbolAddress((void**)&pz,  g_z);
    cudaGetSymbolAddress((void**)&pww, g_ww);
    cudaGetSymbolAddress((void**)&pcw, g_cw);
    cudaGetSymbolAddress((void**)&pw1, g_w1);
    cudaGetSymbolAddress((void**)&pw2, g_w2);
    cudaGetSymbolAddress((void**)&pf0, g_f0);
    cudaGetSymbolAddress((void**)&pf1, g_f1);
    cudaGetSymbolAddress((void**)&pX,  g_X);
    cudaGetSymbolAddress((void**)&pT1, g_T1);
    cudaGetSymbolAddress((void**)&pT2, g_T2);

    const int PB = (NPIX + 255)/256;
    const float INV = 1.0f/(float)HP;

    k_init_tw<<<1, 288>>>();
    k_wnorm<<<24, 32>>>(wienw, wiensc, pww, 25);
    k_wnorm<<<32, 32>>>(convw, scalef, pcw, 25);
    k_wnorm<<<320, 32>>>(w1, s1, pw1, 288);
    k_wnorm<<<160, 32>>>(w2, s2, pw2, 576);

    k_pad<<<dim3(PB, NB), 256>>>(x);
    k_alphas<<<1, 288>>>(bk);
    k_psf1<<<(HP*15 + 255)/256, 256>>>(bk);
    k_psf2<<<PB, 256>>>();
    k_wien1<<<(24*HP*5 + 255)/256, 256>>>();
    k_S<<<PB, 256>>>();

    // fft2(xp) -> X  (2 planes)
    k_dft_rows_real<<<dim3(HP, NB), 288>>>(pxp, pT1);
    k_dft_cols_c   <<<dim3(HP, NB), 288>>>(pT1, pX, 1.f, 1.f);
    // blurred = ifft2(X * Hf).real
    k_etprod<<<dim3(PB, NB), 256>>>();
    k_dft_rows_c   <<<dim3(HP, NB), 288>>>(pT2, pT1, -1.f, INV);
    k_dft_cols_real<<<dim3(HP, NB), 288>>>(pT1, pz, -1.f, INV);
    k_etapply<<<dim3(PB, NB), 256>>>();

    // Y = fft2(xp) -> X
    k_dft_rows_real<<<dim3(HP, NB), 288>>>(pxp, pT1);
    k_dft_cols_c   <<<dim3(HP, NB), 288>>>(pT1, pX, 1.f, 1.f);

    k_amp<<<4, 256>>>(alpha);
    k_cstdn<<<1, 32>>>(stdn);

    // z = ifft2(T * Y).real  (8 planes)
    k_wprod<<<dim3(PB, ND), 256>>>(alpha);
    k_dft_rows_c   <<<dim3(HP, ND), 288>>>(pT2, pT1, -1.f, INV);
    k_dft_cols_real<<<dim3(HP, ND), 288>>>(pT1, pz, -1.f, INV);

    // CNN
    k_conv1<<<dim3(17,17,ND), dim3(16,16)>>>(biasf);
    for (int i = 0; i < 5; ++i){
        k_conv3x3<32><<<dim3(9,9,ND*8), dim3(16,16)>>>(
            pf0, pw1 + (size_t)i*64*32*9, b1 + i*64, p1 + i*32, nullptr, pf1, 8);
        k_conv3x3<64><<<dim3(9,9,ND*4), dim3(16,16)>>>(
            pf1, pw2 + (size_t)i*32*64*9, b2 + i*32, p2 + i*64,
            (i == 0) ? pf0 : nullptr, pf0, 4);
    }
    k_convT<<<dim3(17,17,ND), dim3(16,16)>>>(pf0, biast);

    k_nrm<<<ND, 256>>>();
    k_scl<<<1, 32>>>(aproj);
    k_final<<<dim3(256, NB), 256>>>(mw, outp);
}

// round 6
// speedup vs baseline: 3.3397x; 2.5643x over previous
#include <cuda_runtime.h>
#include <math.h>

#define HP   270
#define NPIX 72900
#define NB   2
#define ND   8
#define HIN  256

typedef unsigned long long u64;
typedef unsigned int u32;

__device__ float  g_xp[NB*NPIX];
__device__ float2 g_X [NB*NPIX];
__device__ float2 g_T1[ND*NPIX];
__device__ float2 g_T2[ND*NPIX];
__device__ float2 g_Hf[NPIX];
__device__ float  g_S [NPIX];
__device__ float2 g_tw[HP];
__device__ float2 g_tempB[HP*15];
__device__ float2 g_tempG[24*HP*5];
__device__ float  g_ah[HP];
__device__ float  g_aw[HP];
__device__ float  g_z [ND*NPIX];
__device__ float  g_ww[24*25];
__device__ float  g_cw[32*25];
__device__ float  g_w1[5*64*32*9];
__device__ float  g_w2[5*32*64*9];
__device__ float  g_f0[ND*32*NPIX];
__device__ float  g_f1[ND*64*NPIX];
__device__ float  g_ct[ND*NPIX];
__device__ float  g_amp[4];
__device__ float  g_cstdn[ND];
__device__ float  g_nrm2[ND];
__device__ float  g_scl[ND];

static __device__ __forceinline__ int refl(int i, int n){
    if (i < 0)  i = -i - 1;
    if (i >= n) i = 2*n - 1 - i;
    return i;
}

static __device__ __forceinline__ u64 pack2(float lo, float hi){
    u64 r;
    asm("mov.b64 %0, {%1, %2};" : "=l"(r) : "f"(lo), "f"(hi));
    return r;
}
static __device__ __forceinline__ u64 ffma2(u64 a, u64 b, u64 c){
    u64 d;
    asm("fma.rn.f32x2 %0, %1, %2, %3;" : "=l"(d) : "l"(a), "l"(b), "l"(c));
    return d;
}
static __device__ __forceinline__ float2 unpack2(u64 v){
    float lo, hi;
    asm("mov.b64 {%0, %1}, %2;" : "=f"(lo), "=f"(hi) : "l"(v));
    return make_float2(lo, hi);
}
static __device__ __forceinline__ float f2tf32(float v){
    u32 u;
    asm("cvt.rna.tf32.f32 %0, %1;" : "=r"(u) : "f"(v));
    return __uint_as_float(u);
}
static __device__ __forceinline__ void mma_tf32(float* d, const u32* a, u32 b0, u32 b1){
    asm volatile(
        "mma.sync.aligned.m16n8k8.row.col.f32.tf32.tf32.f32 "
        "{%0,%1,%2,%3}, {%4,%5,%6,%7}, {%8,%9}, {%0,%1,%2,%3};"
        : "+f"(d[0]), "+f"(d[1]), "+f"(d[2]), "+f"(d[3])
        : "r"(a[0]), "r"(a[1]), "r"(a[2]), "r"(a[3]), "r"(b0), "r"(b1));
}

__global__ void k_init_tw(){
    int t = threadIdx.x;
    if (t < HP){
        double ang = -2.0 * 3.14159265358979323846 * (double)t / (double)HP;
        double s, c; sincos(ang, &s, &c);
        g_tw[t] = make_float2((float)c, (float)s);
    }
}

__global__ void k_pad(const float* __restrict__ x){
    int p = blockIdx.x*256 + threadIdx.x;
    if (p >= NPIX) return;
    int b = blockIdx.y;
    int y = p / HP, xx = p - y*HP;
    g_xp[b*NPIX + p] = x[b*HIN*HIN + refl(y-7,HIN)*HIN + refl(xx-7,HIN)];
}

__global__ void k_alphas(const float* __restrict__ bk){
    __shared__ float ph[15], pw[15], rh[15], rw[15];
    int t = threadIdx.x;
    if (t < 15){
        float s = 0.f, q = 0.f;
        for (int j = 0; j < 15; ++j){ s += bk[t*15+j]; q += bk[j*15+t]; }
        ph[t] = s; pw[t] = q;
    }
    __syncthreads();
    if (t < 15){
        float s = 0.f, q = 0.f;
        for (int j = 0; j + t < 15; ++j){ s += ph[j]*ph[j+t]; q += pw[j]*pw[j+t]; }
        rh[t] = s; rw[t] = q;
    }
    __syncthreads();
    if (t < HP){
        float zh = 0.f, zw = 0.f;
        if (t <= 14)       { zh = rh[t];       zw = rw[t];       }
        else if (t >= 255) { zh = rh[269 - t]; zw = rw[269 - t]; }
        g_ah[t] = 1.f - zh / rh[0];
        g_aw[t] = 1.f - zw / rw[0];
    }
}

__global__ void k_psf1(const float* __restrict__ bk){
    int tid = blockIdx.x*256 + threadIdx.x;
    if (tid >= HP*15) return;
    int u = tid / 15, w = tid - u*15;
    float ax = 0.f, ay = 0.f;
    for (int h = 0; h < 15; ++h){
        int rr = (h >= 7) ? (h - 7) : (h + 263);
        float2 t = g_tw[(u*rr) % HP];
        float v = bk[h*15 + w];
        ax += v*t.x; ay += v*t.y;
    }
    g_tempB[tid] = make_float2(ax, ay);
}

__global__ void k_psf2(){
    int p = blockIdx.x*256 + threadIdx.x;
    if (p >= NPIX) return;
    int u = p / HP, v = p - u*HP;
    float ax = 0.f, ay = 0.f;
    for (int w = 0; w < 15; ++w){
        int rr = (w >= 7) ? (w - 7) : (w + 263);
        float2 t = g_tw[(v*rr) % HP];
        float2 b = g_tempB[u*15 + w];
        ax += b.x*t.x - b.y*t.y;
        ay += b.x*t.y + b.y*t.x;
    }
    g_Hf[p] = make_float2(ax, ay);
}

__global__ void k_wnorm(const float* __restrict__ w, const float* __restrict__ sc,
                        float* __restrict__ out, int sz){
    int ch = blockIdx.x;
    const float* src = w + (size_t)ch*sz;
    int lane = threadIdx.x;
    float s = 0.f;
    for (int i = lane; i < sz; i += 32) s += src[i];
    #pragma unroll
    for (int o = 16; o; o >>= 1) s += __shfl_xor_sync(0xffffffffu, s, o);
    float mean = s / (float)sz;
    float q = 0.f;
    for (int i = lane; i < sz; i += 32){ float v = src[i]-mean; q += v*v; }
    #pragma unroll
    for (int o = 16; o; o >>= 1) q += __shfl_xor_sync(0xffffffffu, q, o);
    float inv = sc[ch] / sqrtf(q);
    for (int i = lane; i < sz; i += 32) out[(size_t)ch*sz + i] = (src[i]-mean)*inv;
}

__global__ void k_wien1(){
    int tid = blockIdx.x*256 + threadIdx.x;
    if (tid >= 24*HP*5) return;
    int o = tid / (HP*5);
    int r = tid - o*HP*5;
    int u = r / 5, w = r - u*5;
    float ax = 0.f, ay = 0.f;
    for (int h = 0; h < 5; ++h){
        int rr = (h >= 2) ? (h - 2) : (h + 268);
        float2 t = g_tw[(u*rr) % HP];
        float v = g_ww[o*25 + h*5 + w];
        ax += v*t.x; ay += v*t.y;
    }
    g_tempG[tid] = make_float2(ax, ay);
}

__global__ void k_S(){
    int p = blockIdx.x*256 + threadIdx.x;
    if (p >= NPIX) return;
    int u = p / HP, v = p - u*HP;
    float2 tws[5];
    #pragma unroll
    for (int w = 0; w < 5; ++w){
        int rr = (w >= 2) ? (w - 2) : (w + 268);
        tws[w] = g_tw[(v*rr) % HP];
    }
    float s = 0.f;
    for (int o = 0; o < 24; ++o){
        float ax = 0.f, ay = 0.f;
        int base = (o*HP + u)*5;
        #pragma unroll
        for (int w = 0; w < 5; ++w){
            float2 g = g_tempG[base + w];
            float2 t = tws[w];
            ax += g.x*t.x - g.y*t.y;
            ay += g.x*t.y + g.y*t.x;
        }
        s += ax*ax + ay*ay;
    }
    g_S[p] = s;
}

__global__ void k_dft_rows_real(const float* __restrict__ in, float2* __restrict__ out){
    __shared__ float sv[HP];
    __shared__ __align__(8) u64 sT[HP];
    int plane = blockIdx.y, row = blockIdx.x;
    const float* src = in + (size_t)plane*NPIX + (size_t)row*HP;
    for (int i = threadIdx.x; i < HP; i += blockDim.x){
        sv[i] = src[i];
        float2 t = g_tw[i];
        sT[i] = pack2(t.x, t.y);
    }
    __syncthreads();
    int k = threadIdx.x;
    if (k < HP){
        u64 acc = 0; int idx = 0;
        #pragma unroll 5
        for (int c = 0; c < HP; ++c){
            float s = sv[c];
            acc = ffma2(pack2(s, s), sT[idx], acc);
            idx += k; if (idx >= HP) idx -= HP;
        }
        float2 a = unpack2(acc);
        out[(size_t)plane*NPIX + (size_t)row*HP + k] = a;
    }
}

__global__ void k_dft_rows_c(const float2* __restrict__ in, float2* __restrict__ out,
                             float sgn, float scale){
    __shared__ __align__(8) float2 sv[HP];
    __shared__ __align__(8) u64 sTA[HP], sTB[HP];
    int plane = blockIdx.y, row = blockIdx.x;
    const float2* src = in + (size_t)plane*NPIX + (size_t)row*HP;
    for (int i = threadIdx.x; i < HP; i += blockDim.x){
        sv[i] = src[i];
        float2 t = g_tw[i];
        float ty = sgn*t.y;
        sTA[i] = pack2(t.x, t.x);
        sTB[i] = pack2(ty, ty);
    }
    __syncthreads();
    int k = threadIdx.x;
    if (k < HP){
        const u64* sv64 = (const u64*)sv;
        u64 P = 0, Q = 0; int idx = 0;
        #pragma unroll 5
        for (int c = 0; c < HP; ++c){
            u64 s = sv64[c];
            P = ffma2(s, sTA[idx], P);
            Q = ffma2(s, sTB[idx], Q);
            idx += k; if (idx >= HP) idx -= HP;
        }
        float2 p = unpack2(P), q = unpack2(Q);
        out[(size_t)plane*NPIX + (size_t)row*HP + k] =
            make_float2((p.x - q.y)*scale, (p.y + q.x)*scale);
    }
}

__global__ void k_dft_cols_c(const float2* __restrict__ in, float2* __restrict__ out,
                             float sgn, float scale){
    __shared__ __align__(8) float2 sv[HP];
    __shared__ __align__(8) u64 sTA[HP], sTB[HP];
    int plane = blockIdx.y, col = blockIdx.x;
    const float2* src = in + (size_t)plane*NPIX + col;
    for (int i = threadIdx.x; i < HP; i += blockDim.x){
        sv[i] = src[(size_t)i*HP];
        float2 t = g_tw[i];
        float ty = sgn*t.y;
        sTA[i] = pack2(t.x, t.x);
        sTB[i] = pack2(ty, ty);
    }
    __syncthreads();
    int k = threadIdx.x;
    if (k < HP){
        const u64* sv64 = (const u64*)sv;
        u64 P = 0, Q = 0; int idx = 0;
        #pragma unroll 5
        for (int c = 0; c < HP; ++c){
            u64 s = sv64[c];
            P = ffma2(s, sTA[idx], P);
            Q = ffma2(s, sTB[idx], Q);
            idx += k; if (idx >= HP) idx -= HP;
        }
        float2 p = unpack2(P), q = unpack2(Q);
        out[(size_t)plane*NPIX + (size_t)k*HP + col] =
            make_float2((p.x - q.y)*scale, (p.y + q.x)*scale);
    }
}

__global__ void k_dft_cols_real(const float2* __restrict__ in, float* __restrict__ out,
                                float sgn, float scale){
    __shared__ __align__(8) float2 sv[HP];
    __shared__ __align__(8) u64 sC[HP];
    int plane = blockIdx.y, col = blockIdx.x;
    const float2* src = in + (size_t)plane*NPIX + col;
    for (int i = threadIdx.x; i < HP; i += blockDim.x){
        sv[i] = src[(size_t)i*HP];
        float2 t = g_tw[i];
        sC[i] = pack2(t.x, -sgn*t.y);
    }
    __syncthreads();
    int k = threadIdx.x;
    if (k < HP){
        const u64* sv64 = (const u64*)sv;
        u64 acc = 0; int idx = 0;
        #pragma unroll 5
        for (int c = 0; c < HP; ++c){
            acc = ffma2(sv64[c], sC[idx], acc);
            idx += k; if (idx >= HP) idx -= HP;
        }
        float2 a = unpack2(acc);
        out[(size_t)plane*NPIX + (size_t)k*HP + col] = (a.x + a.y)*scale;
    }
}

__global__ void k_etprod(){
    int p = blockIdx.x*256 + threadIdx.x;
    if (p >= NPIX) return;
    int b = blockIdx.y;
    float2 X = g_X[(size_t)b*NPIX + p];
    float2 H = g_Hf[p];
    g_T2[(size_t)b*NPIX + p] = make_float2(X.x*H.x - X.y*H.y, X.x*H.y + X.y*H.x);
}

__global__ void k_etapply(){
    int p = blockIdx.x*256 + threadIdx.x;
    if (p >= NPIX) return;
    int b = blockIdx.y;
    int y = p / HP, x = p - y*HP;
    float a = g_ah[y]*g_aw[x];
    float v = g_xp[(size_t)b*NPIX + p];
    g_xp[(size_t)b*NPIX + p] = a*v + (1.f - a)*g_z[(size_t)b*NPIX + p];
}

__global__ void k_amp(const float* __restrict__ alpha){
    __shared__ float red[256];
    int d = blockIdx.x;
    float ad = expf(alpha[d]);
    float s = 0.f;
    for (int p = threadIdx.x; p < NPIX; p += 256){
        float2 H = g_Hf[p];
        float h2 = H.x*H.x + H.y*H.y;
        float den = h2 + ad*g_S[p];
        s += h2 / (den*den);
    }
    red[threadIdx.x] = s; __syncthreads();
    for (int o = 128; o; o >>= 1){
        if (threadIdx.x < o) red[threadIdx.x] += red[threadIdx.x + o];
        __syncthreads();
    }
    if (threadIdx.x == 0) g_amp[d] = red[0] / (float)NPIX;
}

__global__ void k_cstdn(const float* __restrict__ stdn){
    int n = threadIdx.x;
    if (n < ND){
        int b = n >> 2, d = n & 3;
        g_cstdn[n] = sqrtf(stdn[b]*stdn[b]*g_amp[d]);
    }
}

__global__ void k_wprod(const float* __restrict__ alpha){
    int p = blockIdx.x*256 + threadIdx.x;
    if (p >= NPIX) return;
    int n = blockIdx.y;
    int b = n >> 2, d = n & 3;
    float2 H = g_Hf[p];
    float ad = expf(alpha[d]);
    float den = H.x*H.x + H.y*H.y + ad*g_S[p];
    float Tx =  H.x/den;
    float Ty = -H.y/den;
    float2 Y = g_X[(size_t)b*NPIX + p];
    g_T2[(size_t)n*NPIX + p] = make_float2(Tx*Y.x - Ty*Y.y, Tx*Y.y + Ty*Y.x);
}

__global__ __launch_bounds__(256) void k_conv1(const float* __restrict__ bias){
    __shared__ float s_in[20*20];
    __shared__ float s_w[32*25];
    int n = blockIdx.z;
    int ty = threadIdx.y, tx = threadIdx.x;
    int tid = ty*16 + tx;
    int y0 = blockIdx.y*16 - 2, x0 = blockIdx.x*16 - 2;
    const float* src = g_z + (size_t)n*NPIX;
    for (int i = tid; i < 400; i += 256){
        int r = i / 20, c = i - r*20;
        s_in[i] = src[refl(y0+r,HP)*HP + refl(x0+c,HP)];
    }
    for (int i = tid; i < 800; i += 256) s_w[i] = g_cw[i];
    __syncthreads();
    float acc[32];
    #pragma unroll
    for (int o = 0; o < 32; ++o) acc[o] = bias[o];
    #pragma unroll
    for (int ky = 0; ky < 5; ++ky)
        #pragma unroll
        for (int kx = 0; kx < 5; ++kx){
            float v = s_in[(ty+ky)*20 + tx + kx];
            #pragma unroll
            for (int o = 0; o < 32; ++o) acc[o] = fmaf(v, s_w[o*25 + ky*5 + kx], acc[o]);
        }
    int oy = blockIdx.y*16 + ty, ox = blockIdx.x*16 + tx;
    if (oy < HP && ox < HP){
        #pragma unroll
        for (int o = 0; o < 32; ++o)
            g_f0[((size_t)n*32 + o)*NPIX + oy*HP + ox] = acc[o];
    }
}

// ---- tf32 mma.sync implicit-GEMM 3x3 conv ------------------------------
// Block: 16x16 px tile, all COUT channels, 8 warps (256 thr).
// Warp w owns rows 2w..2w+1 of the tile (4 n-tiles of 8 px) x COUT.
// K staged in 8-cin chunks; per chunk: 9 taps x 1 k-slice mma accumulation.
template<int CIN, int COUT>
__global__ __launch_bounds__(256) void k_mma_conv(
    const float* __restrict__ in, const float* __restrict__ wn,
    const float* __restrict__ bias, const float* __restrict__ prelu,
    const float* __restrict__ skip, float* __restrict__ out)
{
    constexpr int MT  = COUT/16;
    constexpr int NCH = CIN/8;
    __shared__ float s_in[8*328];        // [cin8][18*18], cin stride 328 (pad)
    __shared__ float w_s[9*COUT*12];     // [tap][oc][cin8 pad->12]

    int n  = blockIdx.z;
    int y0 = blockIdx.y*16, x0 = blockIdx.x*16;
    int tid  = threadIdx.x;
    int lane = tid & 31, wp = tid >> 5;
    int gid  = lane >> 2, tig = lane & 3;

    float d[MT][4][4];
    #pragma unroll
    for (int m = 0; m < MT; ++m){
        float blo = bias[m*16 + gid];
        float bhi = bias[m*16 + gid + 8];
        #pragma unroll
        for (int nt = 0; nt < 4; ++nt){
            d[m][nt][0] = blo; d[m][nt][1] = blo;
            d[m][nt][2] = bhi; d[m][nt][3] = bhi;
        }
    }

    const float* inb = in + (size_t)n*CIN*NPIX;
    for (int ck = 0; ck < NCH; ++ck){
        __syncthreads();
        // stage weights: w_s[tap][oc][ci] = wn[oc][ck*8+ci][tap], tf32-rounded
        for (int i = tid; i < 9*COUT*8; i += 256){
            int tap = i / (COUT*8);
            int r   = i - tap*COUT*8;
            int oc  = r >> 3, ci = r & 7;
            float v = wn[((size_t)oc*CIN + ck*8 + ci)*9 + tap];
            w_s[(tap*COUT + oc)*12 + ci] = f2tf32(v);
        }
        // stage input tile 18x18 with halo, PReLU, tf32-rounded
        for (int i = tid; i < 8*324; i += 256){
            int ci = i / 324;
            int j  = i - ci*324;
            int yy = j / 18, xx = j - yy*18;
            int cin = ck*8 + ci;
            float v = inb[(size_t)cin*NPIX + refl(y0-1+yy,HP)*HP + refl(x0-1+xx,HP)];
            float sl = prelu[cin];
            v = (v >= 0.f) ? v : v*sl;
            s_in[ci*328 + yy*18 + xx] = f2tf32(v);
        }
        __syncthreads();

        #pragma unroll
        for (int tap = 0; tap < 9; ++tap){
            int ky = tap/3, kx = tap - 3*(tap/3);
            u32 a[MT][4];
            #pragma unroll
            for (int m = 0; m < MT; ++m){
                int base = (tap*COUT + m*16 + gid)*12 + tig;
                a[m][0] = __float_as_uint(w_s[base]);
                a[m][1] = __float_as_uint(w_s[base + 8*12]);
                a[m][2] = __float_as_uint(w_s[base + 4]);
                a[m][3] = __float_as_uint(w_s[base + 8*12 + 4]);
            }
            #pragma unroll
            for (int nt = 0; nt < 4; ++nt){
                int rr  = 2*wp + (nt >> 1);
                int yy  = rr + ky;
                int xxb = (nt & 1)*8 + gid + kx;
                u32 b0 = __float_as_uint(s_in[tig*328 + yy*18 + xxb]);
                u32 b1 = __float_as_uint(s_in[(tig+4)*328 + yy*18 + xxb]);
                #pragma unroll
                for (int m = 0; m < MT; ++m)
                    mma_tf32(d[m][nt], a[m], b0, b1);
            }
        }
    }

    // store (d0,d1) at (oc, y, x..x+1) and (d2,d3) at (oc+8, ...)
    #pragma unroll
    for (int m = 0; m < MT; ++m){
        #pragma unroll
        for (int nt = 0; nt < 4; ++nt){
            int y = y0 + 2*wp + (nt >> 1);
            int x = x0 + (nt & 1)*8 + 2*tig;
            if (y < HP && x < HP){
                int oc = m*16 + gid;
                size_t p0 = ((size_t)n*COUT + oc)*NPIX + (size_t)y*HP + x;
                size_t p1 = p0 + (size_t)8*NPIX;
                float2 v0 = make_float2(d[m][nt][0], d[m][nt][1]);
                float2 v1 = make_float2(d[m][nt][2], d[m][nt][3]);
                if (skip){
                    float2 s0 = *(const float2*)(skip + p0);
                    float2 s1 = *(const float2*)(skip + p1);
                    v0.x += s0.x; v0.y += s0.y;
                    v1.x += s1.x; v1.y += s1.y;
                }
                *(float2*)(out + p0) = v0;
                *(float2*)(out + p1) = v1;
            }
        }
    }
}

__global__ __launch_bounds__(256) void k_convT(const float* __restrict__ in,
                                               const float* __restrict__ biasT){
    __shared__ float s_in[20*20];
    __shared__ float s_w[25];
    int n = blockIdx.z;
    int ty = threadIdx.y, tx = threadIdx.x;
    int tid = ty*16 + tx;
    int y0 = blockIdx.y*16, x0 = blockIdx.x*16;
    float acc = biasT[0];
    for (int oc = 0; oc < 32; ++oc){
        __syncthreads();
        const float* src = in + ((size_t)n*32 + oc)*NPIX;
        for (int i = tid; i < 400; i += 256){
            int r = i / 20, c = i - r*20;
            int yy = y0 - 2 + r, xx = x0 - 2 + c;
            s_in[i] = (yy >= 0 && yy < HP && xx >= 0 && xx < HP) ? src[yy*HP + xx] : 0.f;
        }
        if (tid < 25) s_w[tid] = g_cw[oc*25 + tid];
        __syncthreads();
        #pragma unroll
        for (int u = 0; u < 5; ++u)
            #pragma unroll
            for (int v = 0; v < 5; ++v)
                acc = fmaf(s_in[(ty + 4 - u)*20 + tx + 4 - v], s_w[u*5 + v], acc);
    }
    int oy = y0 + ty, ox = x0 + tx;
    if (oy < HP && ox < HP) g_ct[(size_t)n*NPIX + oy*HP + ox] = acc;
}

__global__ void k_nrm(){
    __shared__ float red[256];
    int n = blockIdx.x;
    float s = 0.f;
    for (int p = threadIdx.x; p < NPIX; p += 256){
        float v = g_ct[(size_t)n*NPIX + p];
        s += v*v;
    }
    red[threadIdx.x] = s; __syncthreads();
    for (int o = 128; o; o >>= 1){
        if (threadIdx.x < o) red[threadIdx.x] += red[threadIdx.x + o];
        __syncthreads();
    }
    if (threadIdx.x == 0) g_nrm2[n] = red[0];
}

__global__ void k_scl(const float* __restrict__ ap){
    int n = threadIdx.x;
    if (n < ND){
        float eps = expf(ap[0]) * g_cstdn[n] * sqrtf((float)(NPIX - 1));
        float nr  = sqrtf(g_nrm2[n]);
        g_scl[n] = (nr > eps) ? eps / fmaxf(nr, 1e-12f) : 1.f;
    }
}

__global__ void k_final(const float* __restrict__ mw, float* __restrict__ outp){
    int b = blockIdx.y;
    int p = blockIdx.x*256 + threadIdx.x;
    int y = p >> 8, x = p & 255;
    size_t q = (size_t)(y + 7)*HP + (x + 7);
    float acc = 0.f;
    #pragma unroll
    for (int d = 0; d < 4; ++d){
        int n = b*4 + d;
        float r = g_z[(size_t)n*NPIX + q] - g_ct[(size_t)n*NPIX + q]*g_scl[n];
        r = fminf(fmaxf(r, 0.f), 255.f);
        acc += mw[d]*r;
    }
    outp[(size_t)b*65536 + p] = acc;
}

extern "C" void kernel_launch(void* const* d_in, const int* in_sizes, int n_in,
                              void* d_out, int out_size){
    const float* x      = (const float*)d_in[0];
    const float* bk     = (const float*)d_in[1];
    const float* stdn   = (const float*)d_in[2];
    const float* wienw  = (const float*)d_in[3];
    const float* wiensc = (const float*)d_in[4];
    const float* alpha  = (const float*)d_in[5];
    const float* convw  = (const float*)d_in[6];
    const float* scalef = (const float*)d_in[7];
    const float* biasf  = (const float*)d_in[8];
    const float* biast  = (const float*)d_in[9];
    const float* p1     = (const float*)d_in[10];
    const float* w1     = (const float*)d_in[11];
    const float* s1     = (const float*)d_in[12];
    const float* b1     = (const float*)d_in[13];
    const float* p2     = (const float*)d_in[14];
    const float* w2     = (const float*)d_in[15];
    const float* s2     = (const float*)d_in[16];
    const float* b2     = (const float*)d_in[17];
    const float* aproj  = (const float*)d_in[18];
    const float* mw     = (const float*)d_in[19];
    float* outp = (float*)d_out;

    float *pxp, *pz, *pww, *pcw, *pw1, *pw2, *pf0, *pf1;
    float2 *pX, *pT1, *pT2;
    cudaGetSymbolAddress((void**)&pxp, g_xp);
    cudaGetSymbolAddress((void**)&pz,  g_z);
    cudaGetSymbolAddress((void**)&pww, g_ww);
    cudaGetSymbolAddress((void**)&pcw, g_cw);
    cudaGetSymbolAddress((void**)&pw1, g_w1);
    cudaGetSymbolAddress((void**)&pw2, g_w2);
    cudaGetSymbolAddress((void**)&pf0, g_f0);
    cudaGetSymbolAddress((void**)&pf1, g_f1);
    cudaGetSymbolAddress((void**)&pX,  g_X);
    cudaGetSymbolAddress((void**)&pT1, g_T1);
    cudaGetSymbolAddress((void**)&pT2, g_T2);

    const int PB = (NPIX + 255)/256;
    const float INV = 1.0f/(float)HP;

    k_init_tw<<<1, 288>>>();
    k_wnorm<<<24, 32>>>(wienw, wiensc, pww, 25);
    k_wnorm<<<32, 32>>>(convw, scalef, pcw, 25);
    k_wnorm<<<320, 32>>>(w1, s1, pw1, 288);
    k_wnorm<<<160, 32>>>(w2, s2, pw2, 576);

    k_pad<<<dim3(PB, NB), 256>>>(x);
    k_alphas<<<1, 288>>>(bk);
    k_psf1<<<(HP*15 + 255)/256, 256>>>(bk);
    k_psf2<<<PB, 256>>>();
    k_wien1<<<(24*HP*5 + 255)/256, 256>>>();
    k_S<<<PB, 256>>>();

    // fft2(xp) -> X  (2 planes)
    k_dft_rows_real<<<dim3(HP, NB), 288>>>(pxp, pT1);
    k_dft_cols_c   <<<dim3(HP, NB), 288>>>(pT1, pX, 1.f, 1.f);
    // blurred = ifft2(X * Hf).real
    k_etprod<<<dim3(PB, NB), 256>>>();
    k_dft_rows_c   <<<dim3(HP, NB), 288>>>(pT2, pT1, -1.f, INV);
    k_dft_cols_real<<<dim3(HP, NB), 288>>>(pT1, pz, -1.f, INV);
    k_etapply<<<dim3(PB, NB), 256>>>();

    // Y = fft2(xp) -> X
    k_dft_rows_real<<<dim3(HP, NB), 288>>>(pxp, pT1);
    k_dft_cols_c   <<<dim3(HP, NB), 288>>>(pT1, pX, 1.f, 1.f);

    k_amp<<<4, 256>>>(alpha);
    k_cstdn<<<1, 32>>>(stdn);

    // z = ifft2(T * Y).real  (8 planes)
    k_wprod<<<dim3(PB, ND), 256>>>(alpha);
    k_dft_rows_c   <<<dim3(HP, ND), 288>>>(pT2, pT1, -1.f, INV);
    k_dft_cols_real<<<dim3(HP, ND), 288>>>(pT1, pz, -1.f, INV);

    // CNN (tensor-core tf32 conv stack)
    k_conv1<<<dim3(17,17,ND), dim3(16,16)>>>(biasf);
    for (int i = 0; i < 5; ++i){
        k_mma_conv<32,64><<<dim3(17,17,ND), 256>>>(
            pf0, pw1 + (size_t)i*64*32*9, b1 + i*64, p1 + i*32, nullptr, pf1);
        k_mma_conv<64,32><<<dim3(17,17,ND), 256>>>(
            pf1, pw2 + (size_t)i*32*64*9, b2 + i*32, p2 + i*64,
            (i == 0) ? pf0 : nullptr, pf0);
    }
    k_convT<<<dim3(17,17,ND), dim3(16,16)>>>(pf0, biast);

    k_nrm<<<ND, 256>>>();
    k_scl<<<1, 32>>>(aproj);
    k_final<<<dim3(256, NB), 256>>>(mw, outp);
}

// round 7
// speedup vs baseline: 5.0030x; 1.4980x over previous
#include <cuda_runtime.h>
#include <math.h>

#define HP   270
#define NPIX 72900
#define NB   2
#define ND   8
#define HIN  256

typedef unsigned long long u64;
typedef unsigned int u32;

__device__ float  g_xp[NB*NPIX];
__device__ float2 g_X [NB*NPIX];
__device__ float2 g_T1[ND*NPIX];
__device__ float2 g_T2[ND*NPIX];
__device__ float2 g_Hf[NPIX];
__device__ float  g_S [NPIX];
__device__ float2 g_tw[HP];
__device__ float2 g_tempB[HP*15];
__device__ float2 g_tempG[24*HP*5];
__device__ float  g_ah[HP];
__device__ float  g_aw[HP];
__device__ float  g_z [ND*NPIX];
__device__ float  g_ww[24*25];
__device__ float  g_cw[32*25];
__device__ float  g_w1[5*64*32*9];
__device__ float  g_w2[5*32*64*9];
__device__ float  g_f0[ND*32*NPIX];
__device__ float  g_f1[ND*64*NPIX];
__device__ float  g_ct[ND*NPIX];
__device__ float  g_amp[4];
__device__ float  g_cstdn[ND];
__device__ float  g_nrm2[ND];
__device__ float  g_scl[ND];

static __device__ __forceinline__ int refl(int i, int n){
    if (i < 0)  i = -i - 1;
    if (i >= n) i = 2*n - 1 - i;
    return i;
}

static __device__ __forceinline__ u64 pack2(float lo, float hi){
    u64 r;
    asm("mov.b64 %0, {%1, %2};" : "=l"(r) : "f"(lo), "f"(hi));
    return r;
}
static __device__ __forceinline__ u64 ffma2(u64 a, u64 b, u64 c){
    u64 d;
    asm("fma.rn.f32x2 %0, %1, %2, %3;" : "=l"(d) : "l"(a), "l"(b), "l"(c));
    return d;
}
static __device__ __forceinline__ float2 unpack2(u64 v){
    float lo, hi;
    asm("mov.b64 {%0, %1}, %2;" : "=f"(lo), "=f"(hi) : "l"(v));
    return make_float2(lo, hi);
}
static __device__ __forceinline__ float f2tf32(float v){
    u32 u;
    asm("cvt.rna.tf32.f32 %0, %1;" : "=r"(u) : "f"(v));
    return __uint_as_float(u);
}
static __device__ __forceinline__ void mma_tf32(float* d, const u32* a, u32 b0, u32 b1){
    asm volatile(
        "mma.sync.aligned.m16n8k8.row.col.f32.tf32.tf32.f32 "
        "{%0,%1,%2,%3}, {%4,%5,%6,%7}, {%8,%9}, {%0,%1,%2,%3};"
        : "+f"(d[0]), "+f"(d[1]), "+f"(d[2]), "+f"(d[3])
        : "r"(a[0]), "r"(a[1]), "r"(a[2]), "r"(a[3]), "r"(b0), "r"(b1));
}

__global__ void k_init_tw(){
    int t = threadIdx.x;
    if (t < HP){
        double ang = -2.0 * 3.14159265358979323846 * (double)t / (double)HP;
        double s, c; sincos(ang, &s, &c);
        g_tw[t] = make_float2((float)c, (float)s);
    }
}

__global__ void k_pad(const float* __restrict__ x){
    int p = blockIdx.x*256 + threadIdx.x;
    if (p >= NPIX) return;
    int b = blockIdx.y;
    int y = p / HP, xx = p - y*HP;
    g_xp[b*NPIX + p] = x[b*HIN*HIN + refl(y-7,HIN)*HIN + refl(xx-7,HIN)];
}

__global__ void k_alphas(const float* __restrict__ bk){
    __shared__ float ph[15], pw[15], rh[15], rw[15];
    int t = threadIdx.x;
    if (t < 15){
        float s = 0.f, q = 0.f;
        for (int j = 0; j < 15; ++j){ s += bk[t*15+j]; q += bk[j*15+t]; }
        ph[t] = s; pw[t] = q;
    }
    __syncthreads();
    if (t < 15){
        float s = 0.f, q = 0.f;
        for (int j = 0; j + t < 15; ++j){ s += ph[j]*ph[j+t]; q += pw[j]*pw[j+t]; }
        rh[t] = s; rw[t] = q;
    }
    __syncthreads();
    if (t < HP){
        float zh = 0.f, zw = 0.f;
        if (t <= 14)       { zh = rh[t];       zw = rw[t];       }
        else if (t >= 255) { zh = rh[269 - t]; zw = rw[269 - t]; }
        g_ah[t] = 1.f - zh / rh[0];
        g_aw[t] = 1.f - zw / rw[0];
    }
}

__global__ void k_psf1(const float* __restrict__ bk){
    int tid = blockIdx.x*256 + threadIdx.x;
    if (tid >= HP*15) return;
    int u = tid / 15, w = tid - u*15;
    float ax = 0.f, ay = 0.f;
    for (int h = 0; h < 15; ++h){
        int rr = (h >= 7) ? (h - 7) : (h + 263);
        float2 t = g_tw[(u*rr) % HP];
        float v = bk[h*15 + w];
        ax += v*t.x; ay += v*t.y;
    }
    g_tempB[tid] = make_float2(ax, ay);
}

__global__ void k_psf2(){
    int p = blockIdx.x*256 + threadIdx.x;
    if (p >= NPIX) return;
    int u = p / HP, v = p - u*HP;
    float ax = 0.f, ay = 0.f;
    for (int w = 0; w < 15; ++w){
        int rr = (w >= 7) ? (w - 7) : (w + 263);
        float2 t = g_tw[(v*rr) % HP];
        float2 b = g_tempB[u*15 + w];
        ax += b.x*t.x - b.y*t.y;
        ay += b.x*t.y + b.y*t.x;
    }
    g_Hf[p] = make_float2(ax, ay);
}

__global__ void k_wnorm(const float* __restrict__ w, const float* __restrict__ sc,
                        float* __restrict__ out, int sz){
    int ch = blockIdx.x;
    const float* src = w + (size_t)ch*sz;
    int lane = threadIdx.x;
    float s = 0.f;
    for (int i = lane; i < sz; i += 32) s += src[i];
    #pragma unroll
    for (int o = 16; o; o >>= 1) s += __shfl_xor_sync(0xffffffffu, s, o);
    float mean = s / (float)sz;
    float q = 0.f;
    for (int i = lane; i < sz; i += 32){ float v = src[i]-mean; q += v*v; }
    #pragma unroll
    for (int o = 16; o; o >>= 1) q += __shfl_xor_sync(0xffffffffu, q, o);
    float inv = sc[ch] / sqrtf(q);
    for (int i = lane; i < sz; i += 32) out[(size_t)ch*sz + i] = (src[i]-mean)*inv;
}

__global__ void k_wien1(){
    int tid = blockIdx.x*256 + threadIdx.x;
    if (tid >= 24*HP*5) return;
    int o = tid / (HP*5);
    int r = tid - o*HP*5;
    int u = r / 5, w = r - u*5;
    float ax = 0.f, ay = 0.f;
    for (int h = 0; h < 5; ++h){
        int rr = (h >= 2) ? (h - 2) : (h + 268);
        float2 t = g_tw[(u*rr) % HP];
        float v = g_ww[o*25 + h*5 + w];
        ax += v*t.x; ay += v*t.y;
    }
    g_tempG[tid] = make_float2(ax, ay);
}

__global__ void k_S(){
    int p = blockIdx.x*256 + threadIdx.x;
    if (p >= NPIX) return;
    int u = p / HP, v = p - u*HP;
    float2 tws[5];
    #pragma unroll
    for (int w = 0; w < 5; ++w){
        int rr = (w >= 2) ? (w - 2) : (w + 268);
        tws[w] = g_tw[(v*rr) % HP];
    }
    float s = 0.f;
    for (int o = 0; o < 24; ++o){
        float ax = 0.f, ay = 0.f;
        int base = (o*HP + u)*5;
        #pragma unroll
        for (int w = 0; w < 5; ++w){
            float2 g = g_tempG[base + w];
            float2 t = tws[w];
            ax += g.x*t.x - g.y*t.y;
            ay += g.x*t.y + g.y*t.x;
        }
        s += ax*ax + ay*ay;
    }
    g_S[p] = s;
}

// ===== Cooley-Tukey 270 = 27x10 DFT line kernels ======================
// stage A: G[k1*27+n2] = sum_{n1<10} v[27*n1+n2] * tw(27*((n1*k1)%10))
// stage B: X[k] = sum_{n2<27} G[(k%10)*27+n2] * tw((n2*k)%270)

__global__ void k_dft_rows_real(const float* __restrict__ in, float2* __restrict__ out){
    __shared__ float sv[HP];
    __shared__ __align__(8) u64 sTA[HP], sTB[HP], sT10[10], sG[HP];
    int plane = blockIdx.y, row = blockIdx.x;
    const float* src = in + (size_t)plane*NPIX + (size_t)row*HP;
    for (int i = threadIdx.x; i < HP; i += blockDim.x){
        sv[i] = src[i];
        float2 t = g_tw[i];
        sTA[i] = pack2(t.x, t.x);
        sTB[i] = pack2(t.y, t.y);
    }
    if (threadIdx.x < 10){
        float2 t = g_tw[27*threadIdx.x];
        sT10[threadIdx.x] = pack2(t.x, t.y);
    }
    __syncthreads();
    int t = threadIdx.x;
    if (t < HP){
        int n2 = t % 27, k1 = t / 27;
        u64 acc = 0; int idx = 0;
        #pragma unroll
        for (int n1 = 0; n1 < 10; ++n1){
            float s = sv[27*n1 + n2];
            acc = ffma2(pack2(s, s), sT10[idx], acc);
            idx += k1; if (idx >= 10) idx -= 10;
        }
        sG[t] = acc;
    }
    __syncthreads();
    if (t < HP){
        int k1 = t % 10;
        u64 P = 0, Q = 0; int idx = 0;
        #pragma unroll 3
        for (int n2 = 0; n2 < 27; ++n2){
            u64 g = sG[k1*27 + n2];
            P = ffma2(g, sTA[idx], P);
            Q = ffma2(g, sTB[idx], Q);
            idx += t; if (idx >= HP) idx -= HP;
        }
        float2 p = unpack2(P), q = unpack2(Q);
        out[(size_t)plane*NPIX + (size_t)row*HP + t] = make_float2(p.x - q.y, p.y + q.x);
    }
}

template<int ROWS>
__global__ void k_dft_line_c(const float2* __restrict__ in, float2* __restrict__ out,
                             float sgn, float scale){
    __shared__ __align__(8) u64 sv[HP];
    __shared__ __align__(8) u64 sTA[HP], sTB[HP], sG[HP];
    int plane = blockIdx.y, line = blockIdx.x;
    const float2* src = in + (size_t)plane*NPIX + (ROWS ? (size_t)line*HP : (size_t)line);
    for (int i = threadIdx.x; i < HP; i += blockDim.x){
        float2 v = ROWS ? src[i] : src[(size_t)i*HP];
        sv[i] = pack2(v.x, v.y);
        float2 t = g_tw[i];
        float ty = sgn*t.y;
        sTA[i] = pack2(t.x, t.x);
        sTB[i] = pack2(ty, ty);
    }
    __syncthreads();
    int t = threadIdx.x;
    if (t < HP){
        int n2 = t % 27, k1 = t / 27;
        u64 PA = 0, QA = 0; int idx = 0;
        #pragma unroll
        for (int n1 = 0; n1 < 10; ++n1){
            u64 s = sv[27*n1 + n2];
            PA = ffma2(s, sTA[27*idx], PA);
            QA = ffma2(s, sTB[27*idx], QA);
            idx += k1; if (idx >= 10) idx -= 10;
        }
        float2 p = unpack2(PA), q = unpack2(QA);
        sG[t] = pack2(p.x - q.y, p.y + q.x);
    }
    __syncthreads();
    if (t < HP){
        int k1 = t % 10;
        u64 P = 0, Q = 0; int idx = 0;
        #pragma unroll 3
        for (int n2 = 0; n2 < 27; ++n2){
            u64 g = sG[k1*27 + n2];
            P = ffma2(g, sTA[idx], P);
            Q = ffma2(g, sTB[idx], Q);
            idx += t; if (idx >= HP) idx -= HP;
        }
        float2 p = unpack2(P), q = unpack2(Q);
        size_t o = (size_t)plane*NPIX + (ROWS ? ((size_t)line*HP + t) : ((size_t)t*HP + line));
        out[o] = make_float2((p.x - q.y)*scale, (p.y + q.x)*scale);
    }
}

__global__ void k_dft_cols_real(const float2* __restrict__ in, float* __restrict__ out,
                                float sgn, float scale){
    __shared__ __align__(8) u64 sv[HP];
    __shared__ __align__(8) u64 sTA[HP], sTB[HP], sTC[HP], sG[HP];
    int plane = blockIdx.y, col = blockIdx.x;
    const float2* src = in + (size_t)plane*NPIX + col;
    for (int i = threadIdx.x; i < HP; i += blockDim.x){
        float2 v = src[(size_t)i*HP];
        sv[i] = pack2(v.x, v.y);
        float2 t = g_tw[i];
        float ty = sgn*t.y;
        sTA[i] = pack2(t.x, t.x);
        sTB[i] = pack2(ty, ty);
        sTC[i] = pack2(t.x, -ty);
    }
    __syncthreads();
    int t = threadIdx.x;
    if (t < HP){
        int n2 = t % 27, k1 = t / 27;
        u64 PA = 0, QA = 0; int idx = 0;
        #pragma unroll
        for (int n1 = 0; n1 < 10; ++n1){
            u64 s = sv[27*n1 + n2];
            PA = ffma2(s, sTA[27*idx], PA);
            QA = ffma2(s, sTB[27*idx], QA);
            idx += k1; if (idx >= 10) idx -= 10;
        }
        float2 p = unpack2(PA), q = unpack2(QA);
        sG[t] = pack2(p.x - q.y, p.y + q.x);
    }
    __syncthreads();
    if (t < HP){
        int k1 = t % 10;
        u64 acc = 0; int idx = 0;
        #pragma unroll 3
        for (int n2 = 0; n2 < 27; ++n2){
            acc = ffma2(sG[k1*27 + n2], sTC[idx], acc);
            idx += t; if (idx >= HP) idx -= HP;
        }
        float2 a = unpack2(acc);
        out[(size_t)plane*NPIX + (size_t)t*HP + col] = (a.x + a.y)*scale;
    }
}

__global__ void k_etprod(){
    int p = blockIdx.x*256 + threadIdx.x;
    if (p >= NPIX) return;
    int b = blockIdx.y;
    float2 X = g_X[(size_t)b*NPIX + p];
    float2 H = g_Hf[p];
    g_T2[(size_t)b*NPIX + p] = make_float2(X.x*H.x - X.y*H.y, X.x*H.y + X.y*H.x);
}

__global__ void k_etapply(){
    int p = blockIdx.x*256 + threadIdx.x;
    if (p >= NPIX) return;
    int b = blockIdx.y;
    int y = p / HP, x = p - y*HP;
    float a = g_ah[y]*g_aw[x];
    float v = g_xp[(size_t)b*NPIX + p];
    g_xp[(size_t)b*NPIX + p] = a*v + (1.f - a)*g_z[(size_t)b*NPIX + p];
}

__global__ void k_amp(const float* __restrict__ alpha){
    __shared__ float red[256];
    int d = blockIdx.x;
    float ad = expf(alpha[d]);
    float s = 0.f;
    for (int p = threadIdx.x; p < NPIX; p += 256){
        float2 H = g_Hf[p];
        float h2 = H.x*H.x + H.y*H.y;
        float den = h2 + ad*g_S[p];
        s += h2 / (den*den);
    }
    red[threadIdx.x] = s; __syncthreads();
    for (int o = 128; o; o >>= 1){
        if (threadIdx.x < o) red[threadIdx.x] += red[threadIdx.x + o];
        __syncthreads();
    }
    if (threadIdx.x == 0) g_amp[d] = red[0] / (float)NPIX;
}

__global__ void k_cstdn(const float* __restrict__ stdn){
    int n = threadIdx.x;
    if (n < ND){
        int b = n >> 2, d = n & 3;
        g_cstdn[n] = sqrtf(stdn[b]*stdn[b]*g_amp[d]);
    }
}

__global__ void k_wprod(const float* __restrict__ alpha){
    int p = blockIdx.x*256 + threadIdx.x;
    if (p >= NPIX) return;
    int n = blockIdx.y;
    int b = n >> 2, d = n & 3;
    float2 H = g_Hf[p];
    float ad = expf(alpha[d]);
    float den = H.x*H.x + H.y*H.y + ad*g_S[p];
    float Tx =  H.x/den;
    float Ty = -H.y/den;
    float2 Y = g_X[(size_t)b*NPIX + p];
    g_T2[(size_t)n*NPIX + p] = make_float2(Tx*Y.x - Ty*Y.y, Tx*Y.y + Ty*Y.x);
}

__global__ __launch_bounds__(256) void k_conv1(const float* __restrict__ bias){
    __shared__ float s_in[20*20];
    __shared__ __align__(8) u64 s_wp[25*16];   // [tap][ocp]
    int n = blockIdx.z;
    int ty = threadIdx.y, tx = threadIdx.x;
    int tid = ty*16 + tx;
    int y0 = blockIdx.y*16 - 2, x0 = blockIdx.x*16 - 2;
    const float* src = g_z + (size_t)n*NPIX;
    for (int i = tid; i < 400; i += 256){
        int r = i / 20, c = i - r*20;
        s_in[i] = src[refl(y0+r,HP)*HP + refl(x0+c,HP)];
    }
    for (int i = tid; i < 400; i += 256){
        int tap = i >> 4, op = i & 15;
        s_wp[i] = pack2(g_cw[(2*op)*25 + tap], g_cw[(2*op+1)*25 + tap]);
    }
    __syncthreads();
    u64 acc[16];
    #pragma unroll
    for (int op = 0; op < 16; ++op) acc[op] = pack2(bias[2*op], bias[2*op+1]);
    #pragma unroll
    for (int ky = 0; ky < 5; ++ky)
        #pragma unroll
        for (int kx = 0; kx < 5; ++kx){
            float v = s_in[(ty+ky)*20 + tx + kx];
            u64 vv = pack2(v, v);
            int tap = ky*5 + kx;
            #pragma unroll
            for (int op = 0; op < 16; ++op)
                acc[op] = ffma2(vv, s_wp[tap*16 + op], acc[op]);
        }
    int oy = blockIdx.y*16 + ty, ox = blockIdx.x*16 + tx;
    if (oy < HP && ox < HP){
        #pragma unroll
        for (int op = 0; op < 16; ++op){
            float2 v = unpack2(acc[op]);
            g_f0[((size_t)n*32 + 2*op  )*NPIX + oy*HP + ox] = v.x;
            g_f0[((size_t)n*32 + 2*op+1)*NPIX + oy*HP + ox] = v.y;
        }
    }
}

// ---- tf32 mma.sync implicit-GEMM 3x3 conv ------------------------------
template<int CIN, int COUT>
__global__ __launch_bounds__(256) void k_mma_conv(
    const float* __restrict__ in, const float* __restrict__ wn,
    const float* __restrict__ bias, const float* __restrict__ prelu,
    const float* __restrict__ skip, float* __restrict__ out)
{
    constexpr int MT  = COUT/16;
    constexpr int NCH = CIN/8;
    __shared__ float s_in[8*328];
    __shared__ float w_s[9*COUT*12];

    int n  = blockIdx.z;
    int y0 = blockIdx.y*16, x0 = blockIdx.x*16;
    int tid  = threadIdx.x;
    int lane = tid & 31, wp = tid >> 5;
    int gid  = lane >> 2, tig = lane & 3;

    float d[MT][4][4];
    #pragma unroll
    for (int m = 0; m < MT; ++m){
        float blo = bias[m*16 + gid];
        float bhi = bias[m*16 + gid + 8];
        #pragma unroll
        for (int nt = 0; nt < 4; ++nt){
            d[m][nt][0] = blo; d[m][nt][1] = blo;
            d[m][nt][2] = bhi; d[m][nt][3] = bhi;
        }
    }

    const float* inb = in + (size_t)n*CIN*NPIX;
    for (int ck = 0; ck < NCH; ++ck){
        __syncthreads();
        for (int i = tid; i < 9*COUT*8; i += 256){
            int tap = i / (COUT*8);
            int r   = i - tap*COUT*8;
            int oc  = r >> 3, ci = r & 7;
            float v = wn[((size_t)oc*CIN + ck*8 + ci)*9 + tap];
            w_s[(tap*COUT + oc)*12 + ci] = f2tf32(v);
        }
        for (int i = tid; i < 8*324; i += 256){
            int ci = i / 324;
            int j  = i - ci*324;
            int yy = j / 18, xx = j - yy*18;
            int cin = ck*8 + ci;
            float v = inb[(size_t)cin*NPIX + refl(y0-1+yy,HP)*HP + refl(x0-1+xx,HP)];
            float sl = prelu[cin];
            v = (v >= 0.f) ? v : v*sl;
            s_in[ci*328 + yy*18 + xx] = f2tf32(v);
        }
        __syncthreads();

        #pragma unroll
        for (int tap = 0; tap < 9; ++tap){
            int ky = tap/3, kx = tap - 3*(tap/3);
            u32 a[MT][4];
            #pragma unroll
            for (int m = 0; m < MT; ++m){
                int base = (tap*COUT + m*16 + gid)*12 + tig;
                a[m][0] = __float_as_uint(w_s[base]);
                a[m][1] = __float_as_uint(w_s[base + 8*12]);
                a[m][2] = __float_as_uint(w_s[base + 4]);
                a[m][3] = __float_as_uint(w_s[base + 8*12 + 4]);
            }
            #pragma unroll
            for (int nt = 0; nt < 4; ++nt){
                int rr  = 2*wp + (nt >> 1);
                int yy  = rr + ky;
                int xxb = (nt & 1)*8 + gid + kx;
                u32 b0 = __float_as_uint(s_in[tig*328 + yy*18 + xxb]);
                u32 b1 = __float_as_uint(s_in[(tig+4)*328 + yy*18 + xxb]);
                #pragma unroll
                for (int m = 0; m < MT; ++m)
                    mma_tf32(d[m][nt], a[m], b0, b1);
            }
        }
    }

    #pragma unroll
    for (int m = 0; m < MT; ++m){
        #pragma unroll
        for (int nt = 0; nt < 4; ++nt){
            int y = y0 + 2*wp + (nt >> 1);
            int x = x0 + (nt & 1)*8 + 2*tig;
            if (y < HP && x < HP){
                int oc = m*16 + gid;
                size_t p0 = ((size_t)n*COUT + oc)*NPIX + (size_t)y*HP + x;
                size_t p1 = p0 + (size_t)8*NPIX;
                float2 v0 = make_float2(d[m][nt][0], d[m][nt][1]);
                float2 v1 = make_float2(d[m][nt][2], d[m][nt][3]);
                if (skip){
                    float2 s0 = *(const float2*)(skip + p0);
                    float2 s1 = *(const float2*)(skip + p1);
                    v0.x += s0.x; v0.y += s0.y;
                    v1.x += s1.x; v1.y += s1.y;
                }
                *(float2*)(out + p0) = v0;
                *(float2*)(out + p1) = v1;
            }
        }
    }
}

__global__ __launch_bounds__(256) void k_convT(const float* __restrict__ in,
                                               const float* __restrict__ biasT){
    __shared__ __align__(8) u64 s_in2[20*20];
    __shared__ __align__(8) u64 s_wp[25];
    int n = blockIdx.z;
    int ty = threadIdx.y, tx = threadIdx.x;
    int tid = ty*16 + tx;
    int y0 = blockIdx.y*16, x0 = blockIdx.x*16;
    u64 acc2 = 0;
    for (int op = 0; op < 16; ++op){
        __syncthreads();
        const float* src0 = in + ((size_t)n*32 + 2*op)*NPIX;
        const float* src1 = src0 + NPIX;
        for (int i = tid; i < 400; i += 256){
            int r = i / 20, c = i - r*20;
            int yy = y0 - 2 + r, xx = x0 - 2 + c;
            if (yy >= 0 && yy < HP && xx >= 0 && xx < HP){
                size_t o = (size_t)yy*HP + xx;
                s_in2[i] = pack2(src0[o], src1[o]);
            } else s_in2[i] = 0;
        }
        if (tid < 25) s_wp[tid] = pack2(g_cw[(2*op)*25 + tid], g_cw[(2*op+1)*25 + tid]);
        __syncthreads();
        #pragma unroll
        for (int u = 0; u < 5; ++u)
            #pragma unroll
            for (int v = 0; v < 5; ++v)
                acc2 = ffma2(s_in2[(ty + 4 - u)*20 + tx + 4 - v], s_wp[u*5 + v], acc2);
    }
    int oy = y0 + ty, ox = x0 + tx;
    if (oy < HP && ox < HP){
        float2 a = unpack2(acc2);
        g_ct[(size_t)n*NPIX + oy*HP + ox] = biasT[0] + a.x + a.y;
    }
}

__global__ void k_nrm(){
    __shared__ float red[256];
    int n = blockIdx.x;
    float s = 0.f;
    for (int p = threadIdx.x; p < NPIX; p += 256){
        float v = g_ct[(size_t)n*NPIX + p];
        s += v*v;
    }
    red[threadIdx.x] = s; __syncthreads();
    for (int o = 128; o; o >>= 1){
        if (threadIdx.x < o) red[threadIdx.x] += red[threadIdx.x + o];
        __syncthreads();
    }
    if (threadIdx.x == 0) g_nrm2[n] = red[0];
}

__global__ void k_scl(const float* __restrict__ ap){
    int n = threadIdx.x;
    if (n < ND){
        float eps = expf(ap[0]) * g_cstdn[n] * sqrtf((float)(NPIX - 1));
        float nr  = sqrtf(g_nrm2[n]);
        g_scl[n] = (nr > eps) ? eps / fmaxf(nr, 1e-12f) : 1.f;
    }
}

__global__ void k_final(const float* __restrict__ mw, float* __restrict__ outp){
    int b = blockIdx.y;
    int p = blockIdx.x*256 + threadIdx.x;
    int y = p >> 8, x = p & 255;
    size_t q = (size_t)(y + 7)*HP + (x + 7);
    float acc = 0.f;
    #pragma unroll
    for (int d = 0; d < 4; ++d){
        int n = b*4 + d;
        float r = g_z[(size_t)n*NPIX + q] - g_ct[(size_t)n*NPIX + q]*g_scl[n];
        r = fminf(fmaxf(r, 0.f), 255.f);
        acc += mw[d]*r;
    }
    outp[(size_t)b*65536 + p] = acc;
}

extern "C" void kernel_launch(void* const* d_in, const int* in_sizes, int n_in,
                              void* d_out, int out_size){
    const float* x      = (const float*)d_in[0];
    const float* bk     = (const float*)d_in[1];
    const float* stdn   = (const float*)d_in[2];
    const float* wienw  = (const float*)d_in[3];
    const float* wiensc = (const float*)d_in[4];
    const float* alpha  = (const float*)d_in[5];
    const float* convw  = (const float*)d_in[6];
    const float* scalef = (const float*)d_in[7];
    const float* biasf  = (const float*)d_in[8];
    const float* biast  = (const float*)d_in[9];
    const float* p1     = (const float*)d_in[10];
    const float* w1     = (const float*)d_in[11];
    const float* s1     = (const float*)d_in[12];
    const float* b1     = (const float*)d_in[13];
    const float* p2     = (const float*)d_in[14];
    const float* w2     = (const float*)d_in[15];
    const float* s2     = (const float*)d_in[16];
    const float* b2     = (const float*)d_in[17];
    const float* aproj  = (const float*)d_in[18];
    const float* mw     = (const float*)d_in[19];
    float* outp = (float*)d_out;

    float *pxp, *pz, *pww, *pcw, *pw1, *pw2, *pf0, *pf1;
    float2 *pX, *pT1, *pT2;
    cudaGetSymbolAddress((void**)&pxp, g_xp);
    cudaGetSymbolAddress((void**)&pz,  g_z);
    cudaGetSymbolAddress((void**)&pww, g_ww);
    cudaGetSymbolAddress((void**)&pcw, g_cw);
    cudaGetSymbolAddress((void**)&pw1, g_w1);
    cudaGetSymbolAddress((void**)&pw2, g_w2);
    cudaGetSymbolAddress((void**)&pf0, g_f0);
    cudaGetSymbolAddress((void**)&pf1, g_f1);
    cudaGetSymbolAddress((void**)&pX,  g_X);
    cudaGetSymbolAddress((void**)&pT1, g_T1);
    cudaGetSymbolAddress((void**)&pT2, g_T2);

    const int PB = (NPIX + 255)/256;
    const float INV = 1.0f/(float)HP;

    k_init_tw<<<1, 288>>>();
    k_wnorm<<<24, 32>>>(wienw, wiensc, pww, 25);
    k_wnorm<<<32, 32>>>(convw, scalef, pcw, 25);
    k_wnorm<<<320, 32>>>(w1, s1, pw1, 288);
    k_wnorm<<<160, 32>>>(w2, s2, pw2, 576);

    k_pad<<<dim3(PB, NB), 256>>>(x);
    k_alphas<<<1, 288>>>(bk);
    k_psf1<<<(HP*15 + 255)/256, 256>>>(bk);
    k_psf2<<<PB, 256>>>();
    k_wien1<<<(24*HP*5 + 255)/256, 256>>>();
    k_S<<<PB, 256>>>();

    // fft2(xp) -> X  (2 planes)
    k_dft_rows_real<<<dim3(HP, NB), 288>>>(pxp, pT1);
    k_dft_line_c<0><<<dim3(HP, NB), 288>>>(pT1, pX, 1.f, 1.f);
    // blurred = ifft2(X * Hf).real
    k_etprod<<<dim3(PB, NB), 256>>>();
    k_dft_line_c<1><<<dim3(HP, NB), 288>>>(pT2, pT1, -1.f, INV);
    k_dft_cols_real<<<dim3(HP, NB), 288>>>(pT1, pz, -1.f, INV);
    k_etapply<<<dim3(PB, NB), 256>>>();

    // Y = fft2(xp) -> X
    k_dft_rows_real<<<dim3(HP, NB), 288>>>(pxp, pT1);
    k_dft_line_c<0><<<dim3(HP, NB), 288>>>(pT1, pX, 1.f, 1.f);

    k_amp<<<4, 256>>>(alpha);
    k_cstdn<<<1, 32>>>(stdn);

    // z = ifft2(T * Y).real  (8 planes)
    k_wprod<<<dim3(PB, ND), 256>>>(alpha);
    k_dft_line_c<1><<<dim3(HP, ND), 288>>>(pT2, pT1, -1.f, INV);
    k_dft_cols_real<<<dim3(HP, ND), 288>>>(pT1, pz, -1.f, INV);

    // CNN
    k_conv1<<<dim3(17,17,ND), dim3(16,16)>>>(biasf);
    for (int i = 0; i < 5; ++i){
        k_mma_conv<32,64><<<dim3(17,17,ND), 256>>>(
            pf0, pw1 + (size_t)i*64*32*9, b1 + i*64, p1 + i*32, nullptr, pf1);
        k_mma_conv<64,32><<<dim3(17,17,ND), 256>>>(
            pf1, pw2 + (size_t)i*32*64*9, b2 + i*32, p2 + i*64,
            (i == 0) ? pf0 : nullptr, pf0);
    }
    k_convT<<<dim3(17,17,ND), dim3(16,16)>>>(pf0, biast);

    k_nrm<<<ND, 256>>>();
    k_scl<<<1, 32>>>(aproj);
    k_final<<<dim3(256, NB), 256>>>(mw, outp);
}

// round 8
// speedup vs baseline: 5.2945x; 1.0583x over previous
#include <cuda_runtime.h>
#include <math.h>

#define HP   270
#define NPIX 72900
#define NB   2
#define ND   8
#define HIN  256

typedef unsigned long long u64;
typedef unsigned int u32;

__device__ float  g_xp[NB*NPIX];
__device__ float2 g_X [NB*NPIX];
__device__ float2 g_T1[ND*NPIX];
__device__ float2 g_Hf[NPIX];
__device__ float  g_S [NPIX];
__device__ float2 g_tw[HP];
__device__ float2 g_tempB[HP*15];
__device__ float2 g_tempG[24*HP*5];
__device__ float  g_ah[HP];
__device__ float  g_aw[HP];
__device__ float  g_z [ND*NPIX];
__device__ float  g_ww[24*25];
__device__ float  g_cw[32*25];
__device__ float  g_w1[5*64*32*9];
__device__ float  g_w2[5*32*64*9];
__device__ __align__(16) float g_w1t[5*4*9*64*12];
__device__ __align__(16) float g_w2t[5*8*9*32*12];
__device__ float  g_f0[ND*32*NPIX];
__device__ float  g_f1[ND*64*NPIX];
__device__ float  g_ct[ND*NPIX];
__device__ float  g_amp[4];
__device__ float  g_cstdn[ND];
__device__ float  g_nrm2[ND];
__device__ float  g_scl[ND];

static __device__ __forceinline__ int refl(int i, int n){
    if (i < 0)  i = -i - 1;
    if (i >= n) i = 2*n - 1 - i;
    return i;
}

static __device__ __forceinline__ u64 pack2(float lo, float hi){
    u64 r;
    asm("mov.b64 %0, {%1, %2};" : "=l"(r) : "f"(lo), "f"(hi));
    return r;
}
static __device__ __forceinline__ u64 ffma2(u64 a, u64 b, u64 c){
    u64 d;
    asm("fma.rn.f32x2 %0, %1, %2, %3;" : "=l"(d) : "l"(a), "l"(b), "l"(c));
    return d;
}
static __device__ __forceinline__ float2 unpack2(u64 v){
    float lo, hi;
    asm("mov.b64 {%0, %1}, %2;" : "=f"(lo), "=f"(hi) : "l"(v));
    return make_float2(lo, hi);
}
static __device__ __forceinline__ float f2tf32(float v){
    u32 u;
    asm("cvt.rna.tf32.f32 %0, %1;" : "=r"(u) : "f"(v));
    return __uint_as_float(u);
}
static __device__ __forceinline__ void mma_tf32(float* d, const u32* a, u32 b0, u32 b1){
    asm volatile(
        "mma.sync.aligned.m16n8k8.row.col.f32.tf32.tf32.f32 "
        "{%0,%1,%2,%3}, {%4,%5,%6,%7}, {%8,%9}, {%0,%1,%2,%3};"
        : "+f"(d[0]), "+f"(d[1]), "+f"(d[2]), "+f"(d[3])
        : "r"(a[0]), "r"(a[1]), "r"(a[2]), "r"(a[3]), "r"(b0), "r"(b1));
}

__global__ void k_init_tw(){
    int t = threadIdx.x;
    if (t < HP){
        double ang = -2.0 * 3.14159265358979323846 * (double)t / (double)HP;
        double s, c; sincos(ang, &s, &c);
        g_tw[t] = make_float2((float)c, (float)s);
    }
}

__global__ void k_pad(const float* __restrict__ x){
    int p = blockIdx.x*256 + threadIdx.x;
    if (p >= NPIX) return;
    int b = blockIdx.y;
    int y = p / HP, xx = p - y*HP;
    g_xp[b*NPIX + p] = x[b*HIN*HIN + refl(y-7,HIN)*HIN + refl(xx-7,HIN)];
}

__global__ void k_alphas(const float* __restrict__ bk){
    __shared__ float ph[15], pw[15], rh[15], rw[15];
    int t = threadIdx.x;
    if (t < 15){
        float s = 0.f, q = 0.f;
        for (int j = 0; j < 15; ++j){ s += bk[t*15+j]; q += bk[j*15+t]; }
        ph[t] = s; pw[t] = q;
    }
    __syncthreads();
    if (t < 15){
        float s = 0.f, q = 0.f;
        for (int j = 0; j + t < 15; ++j){ s += ph[j]*ph[j+t]; q += pw[j]*pw[j+t]; }
        rh[t] = s; rw[t] = q;
    }
    __syncthreads();
    if (t < HP){
        float zh = 0.f, zw = 0.f;
        if (t <= 14)       { zh = rh[t];       zw = rw[t];       }
        else if (t >= 255) { zh = rh[269 - t]; zw = rw[269 - t]; }
        g_ah[t] = 1.f - zh / rh[0];
        g_aw[t] = 1.f - zw / rw[0];
    }
}

__global__ void k_psf1(const float* __restrict__ bk){
    int tid = blockIdx.x*256 + threadIdx.x;
    if (tid >= HP*15) return;
    int u = tid / 15, w = tid - u*15;
    float ax = 0.f, ay = 0.f;
    for (int h = 0; h < 15; ++h){
        int rr = (h >= 7) ? (h - 7) : (h + 263);
        float2 t = g_tw[(u*rr) % HP];
        float v = bk[h*15 + w];
        ax += v*t.x; ay += v*t.y;
    }
    g_tempB[tid] = make_float2(ax, ay);
}

__global__ void k_psf2(){
    int p = blockIdx.x*256 + threadIdx.x;
    if (p >= NPIX) return;
    int u = p / HP, v = p - u*HP;
    float ax = 0.f, ay = 0.f;
    for (int w = 0; w < 15; ++w){
        int rr = (w >= 7) ? (w - 7) : (w + 263);
        float2 t = g_tw[(v*rr) % HP];
        float2 b = g_tempB[u*15 + w];
        ax += b.x*t.x - b.y*t.y;
        ay += b.x*t.y + b.y*t.x;
    }
    g_Hf[p] = make_float2(ax, ay);
}

__global__ void k_wnorm(const float* __restrict__ w, const float* __restrict__ sc,
                        float* __restrict__ out, int sz){
    int ch = blockIdx.x;
    const float* src = w + (size_t)ch*sz;
    int lane = threadIdx.x;
    float s = 0.f;
    for (int i = lane; i < sz; i += 32) s += src[i];
    #pragma unroll
    for (int o = 16; o; o >>= 1) s += __shfl_xor_sync(0xffffffffu, s, o);
    float mean = s / (float)sz;
    float q = 0.f;
    for (int i = lane; i < sz; i += 32){ float v = src[i]-mean; q += v*v; }
    #pragma unroll
    for (int o = 16; o; o >>= 1) q += __shfl_xor_sync(0xffffffffu, q, o);
    float inv = sc[ch] / sqrtf(q);
    for (int i = lane; i < sz; i += 32) out[(size_t)ch*sz + i] = (src[i]-mean)*inv;
}

// pre-transpose + tf32-round conv weights: [layer][chunk][tap][oc][ci pad12]
template<int CIN, int COUT>
__global__ void k_wprep(const float* __restrict__ wn, float* __restrict__ dst){
    int layer = blockIdx.y;
    const float* w = wn + (size_t)layer*COUT*CIN*9;
    float* d = dst + (size_t)layer*(CIN/8)*9*COUT*12;
    int total = (CIN/8)*9*COUT*8;
    for (int i = blockIdx.x*256 + threadIdx.x; i < total; i += gridDim.x*256){
        int ck  = i / (9*COUT*8);
        int r   = i - ck*9*COUT*8;
        int tap = r / (COUT*8);
        int r2  = r - tap*(COUT*8);
        int oc  = r2 >> 3, ci = r2 & 7;
        d[(((size_t)ck*9 + tap)*COUT + oc)*12 + ci] =
            f2tf32(w[((size_t)oc*CIN + ck*8 + ci)*9 + tap]);
    }
}

__global__ void k_wien1(){
    int tid = blockIdx.x*256 + threadIdx.x;
    if (tid >= 24*HP*5) return;
    int o = tid / (HP*5);
    int r = tid - o*HP*5;
    int u = r / 5, w = r - u*5;
    float ax = 0.f, ay = 0.f;
    for (int h = 0; h < 5; ++h){
        int rr = (h >= 2) ? (h - 2) : (h + 268);
        float2 t = g_tw[(u*rr) % HP];
        float v = g_ww[o*25 + h*5 + w];
        ax += v*t.x; ay += v*t.y;
    }
    g_tempG[tid] = make_float2(ax, ay);
}

__global__ void k_S(){
    int p = blockIdx.x*256 + threadIdx.x;
    if (p >= NPIX) return;
    int u = p / HP, v = p - u*HP;
    float2 tws[5];
    #pragma unroll
    for (int w = 0; w < 5; ++w){
        int rr = (w >= 2) ? (w - 2) : (w + 268);
        tws[w] = g_tw[(v*rr) % HP];
    }
    float s = 0.f;
    for (int o = 0; o < 24; ++o){
        float ax = 0.f, ay = 0.f;
        int base = (o*HP + u)*5;
        #pragma unroll
        for (int w = 0; w < 5; ++w){
            float2 g = g_tempG[base + w];
            float2 t = tws[w];
            ax += g.x*t.x - g.y*t.y;
            ay += g.x*t.y + g.y*t.x;
        }
        s += ax*ax + ay*ay;
    }
    g_S[p] = s;
}

// ===== Cooley-Tukey 270 = 27x10 DFT line kernels ======================

__global__ void k_dft_rows_real(const float* __restrict__ in, float2* __restrict__ out){
    __shared__ float sv[HP];
    __shared__ __align__(8) u64 sTA[HP], sTB[HP], sT10[10], sG[HP];
    int plane = blockIdx.y, row = blockIdx.x;
    const float* src = in + (size_t)plane*NPIX + (size_t)row*HP;
    for (int i = threadIdx.x; i < HP; i += blockDim.x){
        sv[i] = src[i];
        float2 t = g_tw[i];
        sTA[i] = pack2(t.x, t.x);
        sTB[i] = pack2(t.y, t.y);
    }
    if (threadIdx.x < 10){
        float2 t = g_tw[27*threadIdx.x];
        sT10[threadIdx.x] = pack2(t.x, t.y);
    }
    __syncthreads();
    int t = threadIdx.x;
    if (t < HP){
        int n2 = t % 27, k1 = t / 27;
        u64 acc = 0; int idx = 0;
        #pragma unroll
        for (int n1 = 0; n1 < 10; ++n1){
            float s = sv[27*n1 + n2];
            acc = ffma2(pack2(s, s), sT10[idx], acc);
            idx += k1; if (idx >= 10) idx -= 10;
        }
        sG[t] = acc;
    }
    __syncthreads();
    if (t < HP){
        int k1 = t % 10;
        u64 P = 0, Q = 0; int idx = 0;
        #pragma unroll 3
        for (int n2 = 0; n2 < 27; ++n2){
            u64 g = sG[k1*27 + n2];
            P = ffma2(g, sTA[idx], P);
            Q = ffma2(g, sTB[idx], Q);
            idx += t; if (idx >= HP) idx -= HP;
        }
        float2 p = unpack2(P), q = unpack2(Q);
        out[(size_t)plane*NPIX + (size_t)row*HP + t] = make_float2(p.x - q.y, p.y + q.x);
    }
}

// MODE 0: plain line DFT (ROWS selects row/col layout)
// MODE 1: rows over X[plane], multiplied by Hf   (edgetaper blur product)
// MODE 2: rows over X[b], full Wiener T product  (plane n -> b=n>>2, d=n&3)
template<int ROWS, int MODE>
__global__ void k_dft_line_c(const float2* __restrict__ in, float2* __restrict__ out,
                             float sgn, float scale, const float* __restrict__ alpha){
    __shared__ __align__(8) u64 sv[HP];
    __shared__ __align__(8) u64 sTA[HP], sTB[HP], sG[HP];
    int plane = blockIdx.y, line = blockIdx.x;
    int srcplane = (MODE == 2) ? (plane >> 2) : plane;
    const float2* src = in + (size_t)srcplane*NPIX + (ROWS ? (size_t)line*HP : (size_t)line);
    float ad = 0.f;
    if (MODE == 2) ad = expf(alpha[plane & 3]);
    for (int i = threadIdx.x; i < HP; i += blockDim.x){
        float2 v = ROWS ? src[i] : src[(size_t)i*HP];
        if (MODE == 1){
            float2 H = g_Hf[line*HP + i];
            v = make_float2(v.x*H.x - v.y*H.y, v.x*H.y + v.y*H.x);
        } else if (MODE == 2){
            int p = line*HP + i;
            float2 H = g_Hf[p];
            float den = H.x*H.x + H.y*H.y + ad*g_S[p];
            float Tx =  H.x/den, Ty = -H.y/den;
            v = make_float2(Tx*v.x - Ty*v.y, Tx*v.y + Ty*v.x);
        }
        sv[i] = pack2(v.x, v.y);
        float2 t = g_tw[i];
        float ty = sgn*t.y;
        sTA[i] = pack2(t.x, t.x);
        sTB[i] = pack2(ty, ty);
    }
    __syncthreads();
    int t = threadIdx.x;
    if (t < HP){
        int n2 = t % 27, k1 = t / 27;
        u64 PA = 0, QA = 0; int idx = 0;
        #pragma unroll
        for (int n1 = 0; n1 < 10; ++n1){
            u64 s = sv[27*n1 + n2];
            PA = ffma2(s, sTA[27*idx], PA);
            QA = ffma2(s, sTB[27*idx], QA);
            idx += k1; if (idx >= 10) idx -= 10;
        }
        float2 p = unpack2(PA), q = unpack2(QA);
        sG[t] = pack2(p.x - q.y, p.y + q.x);
    }
    __syncthreads();
    if (t < HP){
        int k1 = t % 10;
        u64 P = 0, Q = 0; int idx = 0;
        #pragma unroll 3
        for (int n2 = 0; n2 < 27; ++n2){
            u64 g = sG[k1*27 + n2];
            P = ffma2(g, sTA[idx], P);
            Q = ffma2(g, sTB[idx], Q);
            idx += t; if (idx >= HP) idx -= HP;
        }
        float2 p = unpack2(P), q = unpack2(Q);
        size_t o = (size_t)plane*NPIX + (ROWS ? ((size_t)line*HP + t) : ((size_t)t*HP + line));
        out[o] = make_float2((p.x - q.y)*scale, (p.y + q.x)*scale);
    }
}

__global__ void k_dft_cols_real(const float2* __restrict__ in, float* __restrict__ out,
                                float sgn, float scale){
    __shared__ __align__(8) u64 sv[HP];
    __shared__ __align__(8) u64 sTA[HP], sTB[HP], sTC[HP], sG[HP];
    int plane = blockIdx.y, col = blockIdx.x;
    const float2* src = in + (size_t)plane*NPIX + col;
    for (int i = threadIdx.x; i < HP; i += blockDim.x){
        float2 v = src[(size_t)i*HP];
        sv[i] = pack2(v.x, v.y);
        float2 t = g_tw[i];
        float ty = sgn*t.y;
        sTA[i] = pack2(t.x, t.x);
        sTB[i] = pack2(ty, ty);
        sTC[i] = pack2(t.x, -ty);
    }
    __syncthreads();
    int t = threadIdx.x;
    if (t < HP){
        int n2 = t % 27, k1 = t / 27;
        u64 PA = 0, QA = 0; int idx = 0;
        #pragma unroll
        for (int n1 = 0; n1 < 10; ++n1){
            u64 s = sv[27*n1 + n2];
            PA = ffma2(s, sTA[27*idx], PA);
            QA = ffma2(s, sTB[27*idx], QA);
            idx += k1; if (idx >= 10) idx -= 10;
        }
        float2 p = unpack2(PA), q = unpack2(QA);
        sG[t] = pack2(p.x - q.y, p.y + q.x);
    }
    __syncthreads();
    if (t < HP){
        int k1 = t % 10;
        u64 acc = 0; int idx = 0;
        #pragma unroll 3
        for (int n2 = 0; n2 < 27; ++n2){
            acc = ffma2(sG[k1*27 + n2], sTC[idx], acc);
            idx += t; if (idx >= HP) idx -= HP;
        }
        float2 a = unpack2(acc);
        out[(size_t)plane*NPIX + (size_t)t*HP + col] = (a.x + a.y)*scale;
    }
}

__global__ void k_etapply(){
    int p = blockIdx.x*256 + threadIdx.x;
    if (p >= NPIX) return;
    int b = blockIdx.y;
    int y = p / HP, x = p - y*HP;
    float a = g_ah[y]*g_aw[x];
    float v = g_xp[(size_t)b*NPIX + p];
    g_xp[(size_t)b*NPIX + p] = a*v + (1.f - a)*g_z[(size_t)b*NPIX + p];
}

__global__ void k_amp(const float* __restrict__ alpha){
    __shared__ float red[256];
    int d = blockIdx.x;
    float ad = expf(alpha[d]);
    float s = 0.f;
    for (int p = threadIdx.x; p < NPIX; p += 256){
        float2 H = g_Hf[p];
        float h2 = H.x*H.x + H.y*H.y;
        float den = h2 + ad*g_S[p];
        s += h2 / (den*den);
    }
    red[threadIdx.x] = s; __syncthreads();
    for (int o = 128; o; o >>= 1){
        if (threadIdx.x < o) red[threadIdx.x] += red[threadIdx.x + o];
        __syncthreads();
    }
    if (threadIdx.x == 0) g_amp[d] = red[0] / (float)NPIX;
}

__global__ void k_cstdn(const float* __restrict__ stdn){
    int n = threadIdx.x;
    if (n < ND){
        int b = n >> 2, d = n & 3;
        g_cstdn[n] = sqrtf(stdn[b]*stdn[b]*g_amp[d]);
    }
}

__global__ __launch_bounds__(256) void k_conv1(const float* __restrict__ bias){
    __shared__ float s_in[20*20];
    __shared__ __align__(8) u64 s_wp[25*16];
    int n = blockIdx.z;
    int ty = threadIdx.y, tx = threadIdx.x;
    int tid = ty*16 + tx;
    int y0 = blockIdx.y*16 - 2, x0 = blockIdx.x*16 - 2;
    const float* src = g_z + (size_t)n*NPIX;
    for (int i = tid; i < 400; i += 256){
        int r = i / 20, c = i - r*20;
        s_in[i] = src[refl(y0+r,HP)*HP + refl(x0+c,HP)];
    }
    for (int i = tid; i < 400; i += 256){
        int tap = i >> 4, op = i & 15;
        s_wp[i] = pack2(g_cw[(2*op)*25 + tap], g_cw[(2*op+1)*25 + tap]);
    }
    __syncthreads();
    u64 acc[16];
    #pragma unroll
    for (int op = 0; op < 16; ++op) acc[op] = pack2(bias[2*op], bias[2*op+1]);
    #pragma unroll
    for (int ky = 0; ky < 5; ++ky)
        #pragma unroll
        for (int kx = 0; kx < 5; ++kx){
            float v = s_in[(ty+ky)*20 + tx + kx];
            u64 vv = pack2(v, v);
            int tap = ky*5 + kx;
            #pragma unroll
            for (int op = 0; op < 16; ++op)
                acc[op] = ffma2(vv, s_wp[tap*16 + op], acc[op]);
        }
    int oy = blockIdx.y*16 + ty, ox = blockIdx.x*16 + tx;
    if (oy < HP && ox < HP){
        #pragma unroll
        for (int op = 0; op < 16; ++op){
            float2 v = unpack2(acc[op]);
            g_f0[((size_t)n*32 + 2*op  )*NPIX + oy*HP + ox] = v.x;
            g_f0[((size_t)n*32 + 2*op+1)*NPIX + oy*HP + ox] = v.y;
        }
    }
}

// ---- tf32 mma.sync implicit-GEMM 3x3 conv (prepped weights) -------------
template<int CIN, int COUT>
__global__ __launch_bounds__(256) void k_mma_conv(
    const float* __restrict__ in, const float* __restrict__ wt,
    const float* __restrict__ bias, const float* __restrict__ prelu,
    const float* __restrict__ skip, float* __restrict__ out)
{
    constexpr int MT  = COUT/16;
    constexpr int NCH = CIN/8;
    __shared__ __align__(16) float s_in[8*328];
    __shared__ __align__(16) float w_s[9*COUT*12];

    int n  = blockIdx.z;
    int y0 = blockIdx.y*16, x0 = blockIdx.x*16;
    int tid  = threadIdx.x;
    int lane = tid & 31, wp = tid >> 5;
    int gid  = lane >> 2, tig = lane & 3;

    bool interior = (y0 >= 1) && (y0 <= HP-18) && (x0 >= 1) && (x0 <= HP-18);

    float d[MT][4][4];
    #pragma unroll
    for (int m = 0; m < MT; ++m){
        float blo = bias[m*16 + gid];
        float bhi = bias[m*16 + gid + 8];
        #pragma unroll
        for (int nt = 0; nt < 4; ++nt){
            d[m][nt][0] = blo; d[m][nt][1] = blo;
            d[m][nt][2] = bhi; d[m][nt][3] = bhi;
        }
    }

    const float* inb = in + (size_t)n*CIN*NPIX;
    for (int ck = 0; ck < NCH; ++ck){
        __syncthreads();
        // weights: linear float4 copy from prepped layout
        {
            const float4* ws4 = (const float4*)(wt + (size_t)ck*9*COUT*12);
            float4* wd4 = (float4*)w_s;
            for (int i = tid; i < 9*COUT*3; i += 256) wd4[i] = ws4[i];
        }
        // input: warp wp stages cin plane ck*8+wp (18x18 halo tile + PReLU)
        {
            int cin = ck*8 + wp;
            const float* src = inb + (size_t)cin*NPIX;
            float sl = prelu[cin];
            float* dst = &s_in[wp*328];
            if (interior){
                const float* p0 = src + (size_t)(y0-1)*HP + (x0-1);
                for (int j = lane; j < 324; j += 32){
                    int yy = j / 18, xx = j - yy*18;
                    float v = p0[yy*HP + xx];
                    dst[j] = f2tf32((v >= 0.f) ? v : v*sl);
                }
            } else {
                for (int j = lane; j < 324; j += 32){
                    int yy = j / 18, xx = j - yy*18;
                    float v = src[refl(y0-1+yy,HP)*HP + refl(x0-1+xx,HP)];
                    dst[j] = f2tf32((v >= 0.f) ? v : v*sl);
                }
            }
        }
        __syncthreads();

        #pragma unroll
        for (int tap = 0; tap < 9; ++tap){
            int ky = tap/3, kx = tap - 3*(tap/3);
            u32 a[MT][4];
            #pragma unroll
            for (int m = 0; m < MT; ++m){
                int base = (tap*COUT + m*16 + gid)*12 + tig;
                a[m][0] = __float_as_uint(w_s[base]);
                a[m][1] = __float_as_uint(w_s[base + 8*12]);
                a[m][2] = __float_as_uint(w_s[base + 4]);
                a[m][3] = __float_as_uint(w_s[base + 8*12 + 4]);
            }
            #pragma unroll
            for (int nt = 0; nt < 4; ++nt){
                int rr  = 2*wp + (nt >> 1);
                int yy  = rr + ky;
                int xxb = (nt & 1)*8 + gid + kx;
                u32 b0 = __float_as_uint(s_in[tig*328 + yy*18 + xxb]);
                u32 b1 = __float_as_uint(s_in[(tig+4)*328 + yy*18 + xxb]);
                #pragma unroll
                for (int m = 0; m < MT; ++m)
                    mma_tf32(d[m][nt], a[m], b0, b1);
            }
        }
    }

    #pragma unroll
    for (int m = 0; m < MT; ++m){
        #pragma unroll
        for (int nt = 0; nt < 4; ++nt){
            int y = y0 + 2*wp + (nt >> 1);
            int x = x0 + (nt & 1)*8 + 2*tig;
            if (y < HP && x < HP){
                int oc = m*16 + gid;
                size_t p0 = ((size_t)n*COUT + oc)*NPIX + (size_t)y*HP + x;
                size_t p1 = p0 + (size_t)8*NPIX;
                float2 v0 = make_float2(d[m][nt][0], d[m][nt][1]);
                float2 v1 = make_float2(d[m][nt][2], d[m][nt][3]);
                if (skip){
                    float2 s0 = *(const float2*)(skip + p0);
                    float2 s1 = *(const float2*)(skip + p1);
                    v0.x += s0.x; v0.y += s0.y;
                    v1.x += s1.x; v1.y += s1.y;
                }
                *(float2*)(out + p0) = v0;
                *(float2*)(out + p1) = v1;
            }
        }
    }
}

__global__ __launch_bounds__(256) void k_convT(const float* __restrict__ in,
                                               const float* __restrict__ biasT){
    __shared__ __align__(8) u64 s_in2[20*20];
    __shared__ __align__(8) u64 s_wp[25];
    int n = blockIdx.z;
    int ty = threadIdx.y, tx = threadIdx.x;
    int tid = ty*16 + tx;
    int y0 = blockIdx.y*16, x0 = blockIdx.x*16;
    u64 acc2 = 0;
    for (int op = 0; op < 16; ++op){
        __syncthreads();
        const float* src0 = in + ((size_t)n*32 + 2*op)*NPIX;
        const float* src1 = src0 + NPIX;
        for (int i = tid; i < 400; i += 256){
            int r = i / 20, c = i - r*20;
            int yy = y0 - 2 + r, xx = x0 - 2 + c;
            if (yy >= 0 && yy < HP && xx >= 0 && xx < HP){
                size_t o = (size_t)yy*HP + xx;
                s_in2[i] = pack2(src0[o], src1[o]);
            } else s_in2[i] = 0;
        }
        if (tid < 25) s_wp[tid] = pack2(g_cw[(2*op)*25 + tid], g_cw[(2*op+1)*25 + tid]);
        __syncthreads();
        #pragma unroll
        for (int u = 0; u < 5; ++u)
            #pragma unroll
            for (int v = 0; v < 5; ++v)
                acc2 = ffma2(s_in2[(ty + 4 - u)*20 + tx + 4 - v], s_wp[u*5 + v], acc2);
    }
    int oy = y0 + ty, ox = x0 + tx;
    if (oy < HP && ox < HP){
        float2 a = unpack2(acc2);
        g_ct[(size_t)n*NPIX + oy*HP + ox] = biasT[0] + a.x + a.y;
    }
}

__global__ void k_nrm(){
    __shared__ float red[256];
    int n = blockIdx.x;
    float s = 0.f;
    for (int p = threadIdx.x; p < NPIX; p += 256){
        float v = g_ct[(size_t)n*NPIX + p];
        s += v*v;
    }
    red[threadIdx.x] = s; __syncthreads();
    for (int o = 128; o; o >>= 1){
        if (threadIdx.x < o) red[threadIdx.x] += red[threadIdx.x + o];
        __syncthreads();
    }
    if (threadIdx.x == 0) g_nrm2[n] = red[0];
}

__global__ void k_scl(const float* __restrict__ ap){
    int n = threadIdx.x;
    if (n < ND){
        float eps = expf(ap[0]) * g_cstdn[n] * sqrtf((float)(NPIX - 1));
        float nr  = sqrtf(g_nrm2[n]);
        g_scl[n] = (nr > eps) ? eps / fmaxf(nr, 1e-12f) : 1.f;
    }
}

__global__ void k_final(const float* __restrict__ mw, float* __restrict__ outp){
    int b = blockIdx.y;
    int p = blockIdx.x*256 + threadIdx.x;
    int y = p >> 8, x = p & 255;
    size_t q = (size_t)(y + 7)*HP + (x + 7);
    float acc = 0.f;
    #pragma unroll
    for (int d = 0; d < 4; ++d){
        int n = b*4 + d;
        float r = g_z[(size_t)n*NPIX + q] - g_ct[(size_t)n*NPIX + q]*g_scl[n];
        r = fminf(fmaxf(r, 0.f), 255.f);
        acc += mw[d]*r;
    }
    outp[(size_t)b*65536 + p] = acc;
}

extern "C" void kernel_launch(void* const* d_in, const int* in_sizes, int n_in,
                              void* d_out, int out_size){
    const float* x      = (const float*)d_in[0];
    const float* bk     = (const float*)d_in[1];
    const float* stdn   = (const float*)d_in[2];
    const float* wienw  = (const float*)d_in[3];
    const float* wiensc = (const float*)d_in[4];
    const float* alpha  = (const float*)d_in[5];
    const float* convw  = (const float*)d_in[6];
    const float* scalef = (const float*)d_in[7];
    const float* biasf  = (const float*)d_in[8];
    const float* biast  = (const float*)d_in[9];
    const float* p1     = (const float*)d_in[10];
    const float* w1     = (const float*)d_in[11];
    const float* s1     = (const float*)d_in[12];
    const float* b1     = (const float*)d_in[13];
    const float* p2     = (const float*)d_in[14];
    const float* w2     = (const float*)d_in[15];
    const float* s2     = (const float*)d_in[16];
    const float* b2     = (const float*)d_in[17];
    const float* aproj  = (const float*)d_in[18];
    const float* mw     = (const float*)d_in[19];
    float* outp = (float*)d_out;

    float *pxp, *pz, *pww, *pcw, *pw1, *pw2, *pw1t, *pw2t, *pf0, *pf1;
    float2 *pX, *pT1;
    cudaGetSymbolAddress((void**)&pxp, g_xp);
    cudaGetSymbolAddress((void**)&pz,  g_z);
    cudaGetSymbolAddress((void**)&pww, g_ww);
    cudaGetSymbolAddress((void**)&pcw, g_cw);
    cudaGetSymbolAddress((void**)&pw1, g_w1);
    cudaGetSymbolAddress((void**)&pw2, g_w2);
    cudaGetSymbolAddress((void**)&pw1t, g_w1t);
    cudaGetSymbolAddress((void**)&pw2t, g_w2t);
    cudaGetSymbolAddress((void**)&pf0, g_f0);
    cudaGetSymbolAddress((void**)&pf1, g_f1);
    cudaGetSymbolAddress((void**)&pX,  g_X);
    cudaGetSymbolAddress((void**)&pT1, g_T1);

    const int PB = (NPIX + 255)/256;
    const float INV = 1.0f/(float)HP;

    k_init_tw<<<1, 288>>>();
    k_wnorm<<<24, 32>>>(wienw, wiensc, pww, 25);
    k_wnorm<<<32, 32>>>(convw, scalef, pcw, 25);
    k_wnorm<<<320, 32>>>(w1, s1, pw1, 288);
    k_wnorm<<<160, 32>>>(w2, s2, pw2, 576);
    k_wprep<32,64><<<dim3(72,5), 256>>>(pw1, pw1t);
    k_wprep<64,32><<<dim3(72,5), 256>>>(pw2, pw2t);

    k_pad<<<dim3(PB, NB), 256>>>(x);
    k_alphas<<<1, 288>>>(bk);
    k_psf1<<<(HP*15 + 255)/256, 256>>>(bk);
    k_psf2<<<PB, 256>>>();
    k_wien1<<<(24*HP*5 + 255)/256, 256>>>();
    k_S<<<PB, 256>>>();

    // fft2(xp) -> X  (2 planes)
    k_dft_rows_real<<<dim3(HP, NB), 288>>>(pxp, pT1);
    k_dft_line_c<0,0><<<dim3(HP, NB), 288>>>(pT1, pX, 1.f, 1.f, nullptr);
    // blurred = ifft2(X * Hf).real  (Hf product fused into row pass)
    k_dft_line_c<1,1><<<dim3(HP, NB), 288>>>(pX, pT1, -1.f, INV, nullptr);
    k_dft_cols_real<<<dim3(HP, NB), 288>>>(pT1, pz, -1.f, INV);
    k_etapply<<<dim3(PB, NB), 256>>>();

    // Y = fft2(xp) -> X
    k_dft_rows_real<<<dim3(HP, NB), 288>>>(pxp, pT1);
    k_dft_line_c<0,0><<<dim3(HP, NB), 288>>>(pT1, pX, 1.f, 1.f, nullptr);

    k_amp<<<4, 256>>>(alpha);
    k_cstdn<<<1, 32>>>(stdn);

    // z = ifft2(T * Y).real  (Wiener product fused into row pass, 8 planes)
    k_dft_line_c<1,2><<<dim3(HP, ND), 288>>>(pX, pT1, -1.f, INV, alpha);
    k_dft_cols_real<<<dim3(HP, ND), 288>>>(pT1, pz, -1.f, INV);

    // CNN
    k_conv1<<<dim3(17,17,ND), dim3(16,16)>>>(biasf);
    for (int i = 0; i < 5; ++i){
        k_mma_conv<32,64><<<dim3(17,17,ND), 256>>>(
            pf0, pw1t + (size_t)i*4*9*64*12, b1 + i*64, p1 + i*32, nullptr, pf1);
        k_mma_conv<64,32><<<dim3(17,17,ND), 256>>>(
            pf1, pw2t + (size_t)i*8*9*32*12, b2 + i*32, p2 + i*64,
            (i == 0) ? pf0 : nullptr, pf0);
    }
    k_convT<<<dim3(17,17,ND), dim3(16,16)>>>(pf0, biast);

    k_nrm<<<ND, 256>>>();
    k_scl<<<1, 32>>>(aproj);
    k_final<<<dim3(256, NB), 256>>>(mw, outp);
}